// round 14
// baseline (speedup 1.0000x reference)
#include <cuda_runtime.h>
#include <cuda_bf16.h>
#include <math.h>
#include <stdint.h>

#define BB   4
#define LL   512
#define EE   256
#define KH   8
#define DL   6
#define KNN  4
#define GG   32000
#define LMM  64
#define BL   (BB*LL)          // 2048
#define KE   (KH*EE)          // 2048
#define LK   (LL*KH)          // 4096
#define NXB  (GG/128)         // 250 logits col-blocks
#define NR   (BB*LMM*KNN)     // 1024 head rows

// plane sizes (elements per plane)
#define PXSA  ((long)BL*EE)
#define PXSAT ((long)BB*EE*LL)
#define PQ    ((long)BL*KE)
#define PP    ((long)BB*LK*LL)
#define PY    ((long)BL*KE)
#define PYD   ((long)BL*KE)
#define PWQA  ((long)DL*KE*EE)
#define PWDA  ((long)DL*KE*KE)
#define PWOA  ((long)DL*EE*KE)
#define PEMB  ((long)GG*EE)
#define PKC   ((long)KNN*EE*EE)
#define PWEM  ((long)EE*EE)
#define PLPT  ((long)BB*LMM*EE)
#define PXX1  ((long)BB*LMM*KNN*EE)
#define PTB   ((long)BB*LMM*KNN*LL)
#define PXX2  ((long)BB*LMM*KNN*EE)
#define PV    ((long)BB*LMM*KNN*EE)

// ---------------- static scratch -------------------------------------------
__device__ float g_z    [BL*EE];
__device__ float g_xsa  [BL*EE];
__device__ float g_xsad [BL*EE];
__device__ float g_tmp1 [BL*EE];
__device__ float g_tmp2 [BL*EE];
__device__ float g_xid  [4*BL*EE];                 // 4 split-K slabs
__device__ float g_h    [(long)BB*LK*LL];          // 32 MB fp32
__device__ float g_lse  [NR];
__device__ float g_tl   [NR];                      // target logits
__device__ float g_pmax [(long)NR*NXB];
__device__ float g_psum [(long)NR*NXB];

__device__ __nv_bfloat16 g_xsaP [2*PXSA];
__device__ __nv_bfloat16 g_xsaTP[2*PXSAT];
__device__ __nv_bfloat16 g_qP   [2*PQ];
__device__ __nv_bfloat16 g_pP   [2*PP];
__device__ __nv_bfloat16 g_yP   [2*PY];
__device__ __nv_bfloat16 g_ydP  [2*PYD];
__device__ __nv_bfloat16 g_wqP  [2*PWQA];
__device__ __nv_bfloat16 g_wdP  [2*PWDA];
__device__ __nv_bfloat16 g_woTP [2*PWOA];
__device__ __nv_bfloat16 g_embP [2*PEMB];
__device__ __nv_bfloat16 g_kcP  [2*PKC];
__device__ __nv_bfloat16 g_wemTP[2*PWEM];
__device__ __nv_bfloat16 g_lptP [2*PLPT];
__device__ __nv_bfloat16 g_xx1P [2*PXX1];
__device__ __nv_bfloat16 g_tbP  [2*PTB];
__device__ __nv_bfloat16 g_xx2P [2*PXX2];
__device__ __nv_bfloat16 g_vP   [2*PV];

// ---------------- mma.sync helpers -----------------------------------------
__device__ __forceinline__ uint32_t smem_u32(const void* p) {
    uint32_t a;
    asm("{ .reg .u64 t; cvta.to.shared.u64 t, %1; cvt.u32.u64 %0, t; }" : "=r"(a) : "l"(p));
    return a;
}
__device__ __forceinline__ void ldsm_x4(uint32_t* r, uint32_t addr) {
    asm volatile("ldmatrix.sync.aligned.m8n8.x4.shared.b16 {%0,%1,%2,%3}, [%4];"
        : "=r"(r[0]), "=r"(r[1]), "=r"(r[2]), "=r"(r[3]) : "r"(addr));
}
__device__ __forceinline__ void mma16816(float* c, const uint32_t* a, const uint32_t* b) {
    asm volatile("mma.sync.aligned.m16n8k16.row.col.f32.bf16.bf16.f32 "
        "{%0,%1,%2,%3}, {%4,%5,%6,%7}, {%8,%9}, {%0,%1,%2,%3};"
        : "+f"(c[0]), "+f"(c[1]), "+f"(c[2]), "+f"(c[3])
        : "r"(a[0]), "r"(a[1]), "r"(a[2]), "r"(a[3]), "r"(b[0]), "r"(b[1]));
}
#define CP_ASYNC(dst, src) \
    asm volatile("cp.async.ca.shared.global [%0], [%1], 16;" :: "r"(dst), "l"(src))
#define CP_COMMIT()  asm volatile("cp.async.commit_group;" ::: "memory")
#define CP_WAIT(n)   asm volatile("cp.async.wait_group %0;" :: "n"(n) : "memory")

// ---------------- tc_gemm ---------------------------------------------------
// 128x128 CTA tile, 256 threads, 4x2 warp grid, warp tile 32x64.
// K-tile = 64, 3-stage cp.async pipeline.
// splitK>1: blockIdx.z = chunk, writes slab Cf + chunk*sC (deterministic).
// pmax/psum non-null: fused per-CTA row max / sum-exp partials (LSE).
// Cf==Chi==nullptr with pmax set: LSE-only mode (no C store).
#define LDT 72
#define TILE_B (128*LDT*2)
#define STAGE_B (4*TILE_B)
#define NSTAGE 3
#define TCSM (NSTAGE*STAGE_B)         // 221184
__global__ __launch_bounds__(256, 1) void tc_gemm(
    const __nv_bfloat16* __restrict__ Ah, const __nv_bfloat16* __restrict__ Al,
    const __nv_bfloat16* __restrict__ Bh, const __nv_bfloat16* __restrict__ Bl,
    const float* __restrict__ bias, float* __restrict__ Cf,
    __nv_bfloat16* __restrict__ Chi, __nv_bfloat16* __restrict__ Clo,
    float* __restrict__ pmax, float* __restrict__ psum, int nxb,
    int M, int N, int Kd, long sA, long sB, long sC, float alpha, int doRelu,
    int accFlag, int splitK, int kcTiles)
{
    extern __shared__ char smem[];
    int tid = threadIdx.x, lane = tid & 31, wid = tid >> 5;
    int wm = wid >> 1, wn = wid & 1;
    const int nbAll = Kd >> 6;
    long bz = blockIdx.z;
    int kb0 = 0, kbe = nbAll;
    if (splitK > 1) {
        int c = (int)bz; bz = 0;
        kb0 = c * kcTiles;
        kbe = min(nbAll, kb0 + kcTiles);
        if (Cf) Cf += (long)c * sC;        // slab per chunk
    } else {
        if (Cf) Cf += bz * sC;
    }
    Ah += bz * sA; Al += bz * sA; Bh += bz * sB; Bl += bz * sB;
    if (Chi) { Chi += bz * sC; Clo += bz * sC; }
    int m0 = blockIdx.y * 128, n0 = blockIdx.x * 128;

    const __nv_bfloat16* srcs[4] = { Ah + (long)m0 * Kd, Al + (long)m0 * Kd,
                                     Bh + (long)n0 * Kd, Bl + (long)n0 * Kd };

    auto load_blk = [&](int kb, int st) {
        char* base = smem + st * STAGE_B;
        #pragma unroll
        for (int tI = 0; tI < 4; tI++) {
            const __nv_bfloat16* s = srcs[tI] + (long)kb * 64;
            char* d = base + tI * TILE_B;
            #pragma unroll
            for (int i = 0; i < 4; i++) {
                int idx = tid + i * 256;
                int row = idx >> 3, cb = (idx & 7) * 16;
                uint32_t daddr = smem_u32(d + row * (LDT * 2) + cb);
                CP_ASYNC(daddr, (const char*)(s + (long)row * Kd) + cb);
            }
        }
        CP_COMMIT();
    };

    float acc[2][8][4];
    #pragma unroll
    for (int a = 0; a < 2; a++)
        #pragma unroll
        for (int b = 0; b < 8; b++)
            #pragma unroll
            for (int c = 0; c < 4; c++) acc[a][b][c] = 0.f;

    const int nb = kbe - kb0;
    load_blk(kb0, 0);
    if (nb > 1) load_blk(kb0 + 1, 1);

    for (int t = 0; t < nb; t++) {
        int st = t % NSTAGE;
        if (t + 1 < nb) CP_WAIT(1); else CP_WAIT(0);
        __syncthreads();
        if (t + 2 < nb) load_blk(kb0 + t + 2, (t + 2) % NSTAGE);

        char* base = smem + st * STAGE_B;
        uint32_t baseAh = smem_u32(base);
        uint32_t baseAl = baseAh + TILE_B;
        uint32_t baseBh = baseAh + 2 * TILE_B;
        uint32_t baseBl = baseAh + 3 * TILE_B;

        #pragma unroll
        for (int ks = 0; ks < 4; ks++) {
            uint32_t ah[2][4], al[2][4];
            int arow = wm * 32 + (lane & 15);
            int acb  = ks * 32 + (lane >> 4) * 16;
            #pragma unroll
            for (int tm = 0; tm < 2; tm++) {
                uint32_t off = (arow + tm * 16) * (LDT * 2) + acb;
                ldsm_x4(ah[tm], baseAh + off);
                ldsm_x4(al[tm], baseAl + off);
            }
            uint32_t bh[8][2], bl[8][2];
            int q = lane >> 3;
            int brow_base = wn * 64 + ((q & 2) ? 8 : 0) + (lane & 7);
            int bcb = ks * 32 + (q & 1) * 16;
            #pragma unroll
            for (int p = 0; p < 4; p++) {
                uint32_t off = (brow_base + p * 16) * (LDT * 2) + bcb;
                uint32_t r[4];
                ldsm_x4(r, baseBh + off);
                bh[2*p][0] = r[0]; bh[2*p][1] = r[1]; bh[2*p+1][0] = r[2]; bh[2*p+1][1] = r[3];
                ldsm_x4(r, baseBl + off);
                bl[2*p][0] = r[0]; bl[2*p][1] = r[1]; bl[2*p+1][0] = r[2]; bl[2*p+1][1] = r[3];
            }
            #pragma unroll
            for (int tm = 0; tm < 2; tm++)
                #pragma unroll
                for (int tn = 0; tn < 8; tn++) {
                    mma16816(acc[tm][tn], ah[tm], bh[tn]);
                    mma16816(acc[tm][tn], ah[tm], bl[tn]);
                    mma16816(acc[tm][tn], al[tm], bh[tn]);
                }
        }
    }
    __syncthreads();

    if (Cf || Chi) {
        #pragma unroll
        for (int tm = 0; tm < 2; tm++) {
            #pragma unroll
            for (int half = 0; half < 2; half++) {
                int m = m0 + wm * 32 + tm * 16 + (lane >> 2) + half * 8;
                #pragma unroll
                for (int tn = 0; tn < 8; tn++) {
                    int n = n0 + wn * 64 + tn * 8 + (lane & 3) * 2;
                    float v0 = alpha * acc[tm][tn][half * 2 + 0];
                    float v1 = alpha * acc[tm][tn][half * 2 + 1];
                    if (bias) { v0 += bias[n]; v1 += bias[n + 1]; }
                    if (doRelu) { v0 = fmaxf(v0, 0.f); v1 = fmaxf(v1, 0.f); }
                    long idx = (long)m * N + n;
                    if (Cf) {
                        if (accFlag) { Cf[idx] += v0; Cf[idx + 1] += v1; }
                        else { Cf[idx] = v0; Cf[idx + 1] = v1; }
                    } else {
                        __nv_bfloat16 h0 = __float2bfloat16(v0);
                        __nv_bfloat16 h1 = __float2bfloat16(v1);
                        __nv_bfloat162 hp; hp.x = h0; hp.y = h1;
                        *reinterpret_cast<__nv_bfloat162*>(&Chi[idx]) = hp;
                        __nv_bfloat162 lp;
                        lp.x = __float2bfloat16(v0 - __bfloat162float(h0));
                        lp.y = __float2bfloat16(v1 - __bfloat162float(h1));
                        *reinterpret_cast<__nv_bfloat162*>(&Clo[idx]) = lp;
                    }
                }
            }
        }
    }

    // fused per-CTA row-max / sum-exp partials (LSE)
    if (pmax) {
        float* sm8 = (float*)smem;                    // [128][8]
        float* rowred = (float*)(smem + 128 * 8 * 4); // [128]
        int slot = wn * 4 + (lane & 3);
        __syncthreads();
        #pragma unroll
        for (int tm = 0; tm < 2; tm++)
            #pragma unroll
            for (int half = 0; half < 2; half++) {
                int rl = wm * 32 + tm * 16 + (lane >> 2) + half * 8;
                float lm = -1e30f;
                #pragma unroll
                for (int tn = 0; tn < 8; tn++)
                    #pragma unroll
                    for (int e = 0; e < 2; e++)
                        lm = fmaxf(lm, alpha * acc[tm][tn][half * 2 + e]);
                sm8[rl * 8 + slot] = lm;
            }
        __syncthreads();
        if (tid < 128) {
            float mR = -1e30f;
            #pragma unroll
            for (int i = 0; i < 8; i++) mR = fmaxf(mR, sm8[tid * 8 + i]);
            rowred[tid] = mR;
        }
        __syncthreads();
        #pragma unroll
        for (int tm = 0; tm < 2; tm++)
            #pragma unroll
            for (int half = 0; half < 2; half++) {
                int rl = wm * 32 + tm * 16 + (lane >> 2) + half * 8;
                float rm = rowred[rl];
                float ls = 0.f;
                #pragma unroll
                for (int tn = 0; tn < 8; tn++)
                    #pragma unroll
                    for (int e = 0; e < 2; e++)
                        ls += expf(alpha * acc[tm][tn][half * 2 + e] - rm);
                sm8[rl * 8 + slot] = ls;
            }
        __syncthreads();
        if (tid < 128) {
            float sR = 0.f;
            #pragma unroll
            for (int i = 0; i < 8; i++) sR += sm8[tid * 8 + i];
            long r = m0 + tid;
            pmax[r * nxb + blockIdx.x] = rowred[tid];
            psum[r * nxb + blockIdx.x] = sR;
        }
    }
}

// ---------------- SIMT 64x64 tile core (small fp32 GEMMs) ------------------
__device__ __forceinline__ void gemm64_acc(
    const float* __restrict__ A, const float* __restrict__ Bm, bool transB,
    int N, int Kd, int m0, int n0, int rollL, int rollOff,
    float As[32][64], float Bs[32][64], float acc[4][4])
{
    int tid = threadIdx.x;
    int tx = tid & 15, ty = tid >> 4;
    int arow = tid >> 2, ak0 = (tid & 3) * 8;
    int gm = m0 + arow;
    if (rollL) {
        int g = gm / rollL, l = gm - g * rollL;
        l += rollOff; if (l >= rollL) l -= rollL;
        gm = g * rollL + l;
    }
    const float* Aptr = A + (long)gm * Kd + ak0;
    for (int k0 = 0; k0 < Kd; k0 += 32) {
        #pragma unroll
        for (int i = 0; i < 8; i += 4) {
            float4 v = *(const float4*)(Aptr + k0 + i);
            As[ak0+i+0][arow] = v.x; As[ak0+i+1][arow] = v.y;
            As[ak0+i+2][arow] = v.z; As[ak0+i+3][arow] = v.w;
        }
        if (transB) {
            int br = tid >> 2, bk0 = (tid & 3) * 8;
            const float* Bp = Bm + (long)(n0 + br) * Kd + k0 + bk0;
            #pragma unroll
            for (int i = 0; i < 8; i += 4) {
                float4 v = *(const float4*)(Bp + i);
                Bs[bk0+i+0][br] = v.x; Bs[bk0+i+1][br] = v.y;
                Bs[bk0+i+2][br] = v.z; Bs[bk0+i+3][br] = v.w;
            }
        } else {
            int bk = tid >> 3, bn0 = (tid & 7) * 8;
            const float* Bp = Bm + (long)(k0 + bk) * N + n0 + bn0;
            #pragma unroll
            for (int i = 0; i < 8; i += 4)
                *(float4*)&Bs[bk][bn0 + i] = *(const float4*)(Bp + i);
        }
        __syncthreads();
        #pragma unroll
        for (int k = 0; k < 32; k++) {
            float a[4], b[4];
            *(float4*)a = *(const float4*)&As[k][ty * 4];
            *(float4*)b = *(const float4*)&Bs[k][tx * 4];
            #pragma unroll
            for (int i = 0; i < 4; i++)
                #pragma unroll
                for (int j = 0; j < 4; j++)
                    acc[i][j] += a[i] * b[j];
        }
        __syncthreads();
    }
}

// pair_k: z=0: tmp1 = relu(roll(xsa,+1) @ wt); z=1: tmp2 = relu(roll(xsa,-1) @ wtc^T)
__global__ __launch_bounds__(256) void pair_k(
    const float* __restrict__ xsa, const float* __restrict__ wt,
    const float* __restrict__ wtc, float* __restrict__ tmp1, float* __restrict__ tmp2)
{
    __shared__ float As[32][64];
    __shared__ float Bs[32][64];
    int m0 = blockIdx.y * 64, n0 = blockIdx.x * 64;
    float acc[4][4] = {};
    float* C;
    if (blockIdx.z == 0) {
        gemm64_acc(xsa, wt, false, EE, EE, m0, n0, LL, LL - 1, As, Bs, acc);
        C = tmp1;
    } else {
        gemm64_acc(xsa, wtc, true, EE, EE, m0, n0, LL, 1, As, Bs, acc);
        C = tmp2;
    }
    int tid = threadIdx.x, tx = tid & 15, ty = tid >> 4;
    #pragma unroll
    for (int i = 0; i < 4; i++) {
        int m = m0 + ty * 4 + i;
        #pragma unroll
        for (int j = 0; j < 4; j++) {
            int n = n0 + tx * 4 + j;
            C[(long)m * EE + n] = fmaxf(acc[i][j], 0.f);
        }
    }
}

// sum3_k: xsad = tmp1 @ wtc + tmp2 @ wt^T + z @ wu^T + bt
__global__ __launch_bounds__(256) void sum3_k(
    const float* __restrict__ tmp1, const float* __restrict__ tmp2,
    const float* __restrict__ z, const float* __restrict__ wt,
    const float* __restrict__ wtc, const float* __restrict__ wu,
    const float* __restrict__ bt, float* __restrict__ xsad)
{
    __shared__ float As[32][64];
    __shared__ float Bs[32][64];
    int m0 = blockIdx.y * 64, n0 = blockIdx.x * 64;
    float acc[4][4] = {};
    gemm64_acc(tmp1, wtc, false, EE, EE, m0, n0, 0, 0, As, Bs, acc);
    gemm64_acc(tmp2, wt,  true,  EE, EE, m0, n0, 0, 0, As, Bs, acc);
    gemm64_acc(z,    wu,  true,  EE, EE, m0, n0, 0, 0, As, Bs, acc);
    int tid = threadIdx.x, tx = tid & 15, ty = tid >> 4;
    #pragma unroll
    for (int i = 0; i < 4; i++) {
        int m = m0 + ty * 4 + i;
        #pragma unroll
        for (int j = 0; j < 4; j++) {
            int n = n0 + tx * 4 + j;
            xsad[(long)m * EE + n] = acc[i][j] + bt[n];
        }
    }
}

// ---------------- split / transpose-split ----------------------------------
__global__ void split_k(const float* __restrict__ s, __nv_bfloat16* __restrict__ h,
                        __nv_bfloat16* __restrict__ l, long n)
{
    long i = blockIdx.x * 256L + threadIdx.x;
    if (i < n) {
        float v = s[i];
        __nv_bfloat16 a = __float2bfloat16(v);
        h[i] = a;
        l[i] = __float2bfloat16(v - __bfloat162float(a));
    }
}
__global__ void tsplit_k(const float* __restrict__ s, __nv_bfloat16* __restrict__ h,
                         __nv_bfloat16* __restrict__ l, int R, int C, long sS, long sD)
{
    __shared__ float t[32][33];
    int b = blockIdx.z;
    s += (long)b * sS; h += (long)b * sD; l += (long)b * sD;
    int r0 = blockIdx.y * 32, c0 = blockIdx.x * 32;
    int x = threadIdx.x, y = threadIdx.y;
    #pragma unroll
    for (int i = 0; i < 32; i += 8) t[y + i][x] = s[(long)(r0 + y + i) * C + c0 + x];
    __syncthreads();
    #pragma unroll
    for (int i = 0; i < 32; i += 8) {
        float v = t[x][y + i];
        __nv_bfloat16 a = __float2bfloat16(v);
        long idx = (long)(c0 + y + i) * R + r0 + x;
        h[idx] = a;
        l[idx] = __float2bfloat16(v - __bfloat162float(a));
    }
}

// ---------------- elementwise / reduction kernels --------------------------
__device__ __forceinline__ float blkSum256(float v) {
    __shared__ float sh[8];
    int lane = threadIdx.x & 31, w = threadIdx.x >> 5;
    #pragma unroll
    for (int o = 16; o; o >>= 1) v += __shfl_xor_sync(0xffffffffu, v, o);
    __syncthreads();
    if (lane == 0) sh[w] = v;
    __syncthreads();
    float r = sh[0];
    #pragma unroll
    for (int i = 1; i < 8; i++) r += sh[i];
    return r;
}
__device__ __forceinline__ float blkMax256(float v) {
    __shared__ float sh[8];
    int lane = threadIdx.x & 31, w = threadIdx.x >> 5;
    #pragma unroll
    for (int o = 16; o; o >>= 1) v = fmaxf(v, __shfl_xor_sync(0xffffffffu, v, o));
    __syncthreads();
    if (lane == 0) sh[w] = v;
    __syncthreads();
    float r = sh[0];
    #pragma unroll
    for (int i = 1; i < 8; i++) r = fmaxf(r, sh[i]);
    return r;
}
__device__ __forceinline__ void emit_planes(__nv_bfloat16* h, __nv_bfloat16* l,
                                            long idx, float v) {
    __nv_bfloat16 a = __float2bfloat16(v);
    h[idx] = a;
    l[idx] = __float2bfloat16(v - __bfloat162float(a));
}

__global__ void embed_norm_k(const int* __restrict__ masked, const float* __restrict__ embed,
                             float* __restrict__ z, float* __restrict__ xsa,
                             __nv_bfloat16* __restrict__ xh, __nv_bfloat16* __restrict__ xl)
{
    long row = blockIdx.x; int t = threadIdx.x;
    float v = embed[(long)masked[row] * EE + t];
    float mean = blkSum256(v) * (1.f / EE);
    float d = v - mean;
    float var = fmaxf(blkSum256(d * d) * (1.f / (EE - 1)), 0.f);
    float o = v / (1.f + sqrtf(var));
    long i = row * EE + t;
    z[i] = o;
    xsa[i] = o;
    emit_planes(xh, xl, i, o);
}

__global__ void softmax512_k(const float* __restrict__ h,
                             __nv_bfloat16* __restrict__ ph, __nv_bfloat16* __restrict__ pl)
{
    long row = blockIdx.x;
    const float* p = h + row * 512;
    int t = threadIdx.x;
    float a = p[t], b = p[t + 256];
    float m = blkMax256(fmaxf(a, b));
    float ea = expf(a - m), eb = expf(b - m);
    float s = blkSum256(ea + eb);
    float inv = 1.f / s;
    emit_planes(ph, pl, row * 512 + t, ea * inv);
    emit_planes(ph, pl, row * 512 + t + 256, eb * inv);
}

__global__ void update_k(const float* __restrict__ xsad, const float* __restrict__ xid,
                         float* __restrict__ xsa,
                         __nv_bfloat16* __restrict__ xh, __nv_bfloat16* __restrict__ xl)
{
    long row = blockIdx.x; int t = threadIdx.x;
    long i = row * EE + t;
    const long S = (long)BL * EE;
    float s = xsad[i] + ((xid[i] + xid[i + S]) + (xid[i + 2 * S] + xid[i + 3 * S]));
    float mean = blkSum256(s) * (1.f / EE);
    float d = s - mean;
    float var = fmaxf(blkSum256(d * d) * (1.f / (EE - 1)), 0.f);
    float a = s / (1.f + sqrtf(var));
    float x = xsa[i] + 0.05f * a;
    float mean2 = blkSum256(x) * (1.f / EE);
    float d2 = x - mean2;
    float var2 = fmaxf(blkSum256(d2 * d2) * (1.f / (EE - 1)), 0.f);
    float o = x / (1.f + sqrtf(var2));
    xsa[i] = o;
    emit_planes(xh, xl, i, o);
}

__global__ void gather_lptok_k(const float* __restrict__ xsa, const int* __restrict__ mask,
                               __nv_bfloat16* __restrict__ h, __nv_bfloat16* __restrict__ l)
{
    int r = blockIdx.x;
    int b = r / LMM, lm = r % LMM;
    int pos = mask[b * LMM + lm];
    int t = threadIdx.x;
    float v = xsa[((long)b * LL + pos) * EE + t];
    emit_planes(h, l, (long)r * EE + t, v);
}

__global__ void lse_reduce_k(const float* __restrict__ pmax, const float* __restrict__ psum,
                             float* __restrict__ lse)
{
    long row = blockIdx.x;
    int t = threadIdx.x;
    const float* pm = pmax + row * NXB;
    const float* ps = psum + row * NXB;
    float m = -1e30f;
    for (int i = t; i < NXB; i += 256) m = fmaxf(m, pm[i]);
    m = blkMax256(m);
    float s = 0.f;
    for (int i = t; i < NXB; i += 256) s += ps[i] * expf(pm[i] - m);
    s = blkSum256(s);
    if (!t) lse[row] = m + logf(s);
}

// tgt_dot_k: tl[n] = dot(v[n], embed[tgt]) using the same hi/lo 3-product expansion
__global__ void tgt_dot_k(const __nv_bfloat16* __restrict__ vh, const __nv_bfloat16* __restrict__ vl,
                          const __nv_bfloat16* __restrict__ eh, const __nv_bfloat16* __restrict__ el,
                          const int* __restrict__ unmasked, const int* __restrict__ mask,
                          float* __restrict__ tl)
{
    int n = blockIdx.x;                 // 0..NR-1
    int b = n / (LMM * KNN);
    int lm = (n % (LMM * KNN)) / KNN;
    int pos = mask[b * LMM + lm];
    int tgt = unmasked[b * LL + pos];
    int t = threadIdx.x;
    float a_h = __bfloat162float(vh[(long)n * EE + t]);
    float a_l = __bfloat162float(vl[(long)n * EE + t]);
    float b_h = __bfloat162float(eh[(long)tgt * EE + t]);
    float b_l = __bfloat162float(el[(long)tgt * EE + t]);
    float v = a_h * b_h + a_h * b_l + a_l * b_h;
    v = blkSum256(v);
    if (!t) tl[n] = v;
}

__global__ void final_k(const float* __restrict__ tl, const float* __restrict__ lse,
                        float* __restrict__ out)
{
    int b = blockIdx.x, lm = threadIdx.x;
    float v[KNN]; float m = -1e30f;
    #pragma unroll
    for (int kn = 0; kn < KNN; kn++) {
        int n = b * (LMM * KNN) + lm * KNN + kn;
        v[kn] = tl[n] - lse[n];
        m = fmaxf(m, v[kn]);
    }
    float s = 0.f;
    #pragma unroll
    for (int kn = 0; kn < KNN; kn++) s += expf(v[kn] - m);
    float cent = m + logf(s) - logf((float)KNN);
    __shared__ float sh[LMM];
    sh[lm] = cent; __syncthreads();
    for (int o = 32; o; o >>= 1) { if (lm < o) sh[lm] += sh[lm + o]; __syncthreads(); }
    if (!lm) out[b] = -sh[0] / (float)LMM;
}

// ---------------- host orchestration ---------------------------------------
typedef __nv_bfloat16 bf;
template <typename T> static inline T* sym(const void* s) {
    void* p = nullptr; cudaGetSymbolAddress(&p, s); return (T*)p;
}
static inline void tc(cudaStream_t st, const bf* Ah, const bf* Al, const bf* Bh, const bf* Bl,
                      const float* bias, float* Cf, bf* Ch, bf* Cl,
                      int M, int N, int K, long sA, long sB, long sC, int batch,
                      float alpha, int relu, int accF = 0, int splitK = 1,
                      float* pmax = nullptr, float* psum = nullptr)
{
    int kcT = 1;
    int zdim = batch;
    if (splitK > 1) {
        int nbAll = K >> 6;
        kcT = (nbAll + splitK - 1) / splitK;
        zdim = splitK;
    }
    dim3 g(N / 128, M / 128, zdim);
    tc_gemm<<<g, 256, TCSM, st>>>(Ah, Al, Bh, Bl, bias, Cf, Ch, Cl, pmax, psum, N / 128,
                                  M, N, K, sA, sB, sC, alpha, relu, accF, splitK, kcT);
}

extern "C" void kernel_launch(void* const* d_in, const int* in_sizes, int n_in,
                              void* d_out, int out_size)
{
    const int*   masked   = (const int*)  d_in[0];
    const int*   unmasked = (const int*)  d_in[1];
    const int*   mask     = (const int*)  d_in[2];
    const float* embed    = (const float*)d_in[3];
    const float* Wt       = (const float*)d_in[4];
    const float* bt       = (const float*)d_in[5];
    const float* Wtc      = (const float*)d_in[6];
    const float* Wq       = (const float*)d_in[7];
    const float* Wd       = (const float*)d_in[8];
    const float* Wo       = (const float*)d_in[9];
    const float* Wu       = (const float*)d_in[10];
    const float* Wem      = (const float*)d_in[11];
    const float* Wkc      = (const float*)d_in[12];
    const float* bkc      = (const float*)d_in[13];
    float* out = (float*)d_out;

    static bool inited = false;
    static cudaStream_t s2 = nullptr;
    static cudaEvent_t evFork = nullptr, evS = nullptr;
    if (!inited) {
        cudaFuncSetAttribute(tc_gemm, cudaFuncAttributeMaxDynamicSharedMemorySize, TCSM);
        cudaStreamCreateWithFlags(&s2, cudaStreamNonBlocking);
        cudaEventCreateWithFlags(&evFork, cudaEventDisableTiming);
        cudaEventCreateWithFlags(&evS, cudaEventDisableTiming);
        inited = true;
    }
    cudaStream_t s0 = 0;

    float *z = sym<float>(g_z), *xsa = sym<float>(g_xsa), *xsad = sym<float>(g_xsad);
    float *tmp1 = sym<float>(g_tmp1), *tmp2 = sym<float>(g_tmp2), *xid = sym<float>(g_xid);
    float *h = sym<float>(g_h), *lse = sym<float>(g_lse), *tl = sym<float>(g_tl);
    float *pmax = sym<float>(g_pmax), *psum = sym<float>(g_psum);
    bf *xsaP = sym<bf>(g_xsaP), *xsaTP = sym<bf>(g_xsaTP);
    bf *qP = sym<bf>(g_qP), *pP = sym<bf>(g_pP), *yP = sym<bf>(g_yP), *ydP = sym<bf>(g_ydP);
    bf *wqP = sym<bf>(g_wqP), *wdP = sym<bf>(g_wdP), *woTP = sym<bf>(g_woTP);
    bf *embP = sym<bf>(g_embP), *kcP = sym<bf>(g_kcP), *wemTP = sym<bf>(g_wemTP);
    bf *lptP = sym<bf>(g_lptP), *xx1P = sym<bf>(g_xx1P), *tbP = sym<bf>(g_tbP);
    bf *xx2P = sym<bf>(g_xx2P), *vP = sym<bf>(g_vP);

    embed_norm_k<<<BL, 256, 0, s0>>>(masked, embed, z, xsa, xsaP, xsaP + PXSA);
    split_k<<<(PWQA + 255) / 256, 256, 0, s0>>>(Wq, wqP, wqP + PWQA, PWQA);

    for (int d = 0; d < DL; d++) {
        const float* wt  = Wt  + (long)d * EE * EE;
        const float* btd = bt  + (long)d * EE;
        const float* wtc = Wtc + (long)d * EE * EE;
        const float* wu  = Wu  + (long)d * EE * EE;
        const bf* wqh = wqP + (long)d * KE * EE;  const bf* wql = wqh + PWQA;
        const bf* wdh = wdP + (long)d * KE * KE;  const bf* wdl = wdh + PWDA;
        const bf* woh = woTP + (long)d * EE * KE; const bf* wol = woh + PWOA;

        cudaEventRecord(evFork, s0);
        cudaStreamWaitEvent(s2, evFork, 0);
        if (d == 0) {
            split_k<<<(PWDA + 255) / 256, 256, 0, s2>>>(Wd, wdP, wdP + PWDA, PWDA);
            split_k<<<(PEMB + 255) / 256, 256, 0, s2>>>(embed, embP, embP + PEMB, PEMB);
            split_k<<<(PKC + 255) / 256, 256, 0, s2>>>(Wkc, kcP, kcP + PKC, PKC);
            { dim3 b(32, 8), g(EE / 32, KE / 32, DL);
              tsplit_k<<<g, b, 0, s2>>>(Wo, woTP, woTP + PWOA, KE, EE, (long)KE * EE, (long)EE * KE); }
            { dim3 b(32, 8), g(EE / 32, EE / 32, 1);
              tsplit_k<<<g, b, 0, s2>>>(Wem, wemTP, wemTP + PWEM, EE, EE, 0, 0); }
        }
        { dim3 b(32, 8), g(EE / 32, LL / 32, BB);
          tsplit_k<<<g, b, 0, s2>>>(xsa, xsaTP, xsaTP + PXSAT, LL, EE, (long)LL * EE, (long)EE * LL); }
        { dim3 g(EE / 64, BL / 64, 2);
          pair_k<<<g, 256, 0, s2>>>(xsa, wt, wtc, tmp1, tmp2); }
        { dim3 g(EE / 64, BL / 64, 1);
          sum3_k<<<g, 256, 0, s2>>>(tmp1, tmp2, z, wt, wtc, wu, btd, xsad); }
        cudaEventRecord(evS, s2);

        tc(s0, xsaP, xsaP + PXSA, wqh, wql, nullptr, nullptr, qP, qP + PQ,
           BL, KE, EE, 0, 0, 0, 1, 1.f, 0);
        tc(s0, qP, qP + PQ, xsaP, xsaP + PXSA, nullptr, h, nullptr, nullptr,
           LK, LL, EE, (long)LK * EE, (long)LL * EE, (long)LK * LL, BB, 1.f / 16.f, 0);
        softmax512_k<<<BB * LK, 256, 0, s0>>>(h, pP, pP + PP);

        cudaStreamWaitEvent(s0, evS, 0);

        tc(s0, pP, pP + PP, xsaTP, xsaTP + PXSAT, nullptr, nullptr, yP, yP + PY,
           LK, EE, LL, (long)LK * LL, (long)EE * LL, (long)LK * EE, BB, 1.f, 0);
        tc(s0, yP, yP + PY, wdh, wdl, nullptr, nullptr, ydP, ydP + PYD,
           BL, KE, KE, 0, 0, 0, 1, 1.f, 1);
        // xid = yd @ wo — deterministic split-K=4 into 4 slabs (stride BL*EE)
        tc(s0, ydP, ydP + PYD, woh, wol, nullptr, xid, nullptr, nullptr,
           BL, EE, KE, 0, 0, (long)BL * EE, 1, 1.f, 0, 0, /*splitK=*/4);
        update_k<<<BL, 256, 0, s0>>>(xsad, xid, xsa, xsaP, xsaP + PXSA);
    }

    // ---- head ----
    { dim3 b(32, 8), g(EE / 32, LL / 32, BB);
      tsplit_k<<<g, b, 0, s0>>>(xsa, xsaTP, xsaTP + PXSAT, LL, EE, (long)LL * EE, (long)EE * LL); }
    gather_lptok_k<<<BB * LMM, 256, 0, s0>>>(xsa, mask, lptP, lptP + PLPT);
    tc(s0, lptP, lptP + PLPT, kcP, kcP + PKC, bkc, nullptr, xx1P, xx1P + PXX1,
       BB * LMM, KNN * EE, EE, 0, 0, 0, 1, 1.f, 0);
    tc(s0, xx1P, xx1P + PXX1, xsaP, xsaP + PXSA, nullptr, nullptr, tbP, tbP + PTB,
       LMM * KNN, LL, EE, (long)LMM * KNN * EE, (long)LL * EE, (long)LMM * KNN * LL, BB, 1.f, 0);
    tc(s0, tbP, tbP + PTB, xsaTP, xsaTP + PXSAT, nullptr, nullptr, xx2P, xx2P + PXX2,
       LMM * KNN, EE, LL, (long)LMM * KNN * LL, (long)EE * LL, (long)LMM * KNN * EE, BB, 1.f, 0);
    tc(s0, xx2P, xx2P + PXX2, wemTP, wemTP + PWEM, nullptr, nullptr, vP, vP + PV,
       BB * LMM * KNN, EE, EE, 0, 0, 0, 1, 1.f, 0);
    // logits GEMM: LSE-only mode (no 131MB store)
    tc(s0, vP, vP + PV, embP, embP + PEMB, nullptr, nullptr, nullptr, nullptr,
       NR, GG, EE, 0, 0, 0, 1, 1.f, 0, 0, 1, pmax, psum);
    lse_reduce_k<<<NR, 256, 0, s0>>>(pmax, psum, lse);
    tgt_dot_k<<<NR, 256, 0, s0>>>(vP, vP + PV, embP, embP + PEMB, unmasked, mask, tl);
    final_k<<<BB, LMM, 0, s0>>>(tl, lse, out);
}

// round 15
// speedup vs baseline: 1.0150x; 1.0150x over previous
#include <cuda_runtime.h>
#include <cuda_bf16.h>
#include <math.h>
#include <stdint.h>

#define BB   4
#define LL   512
#define EE   256
#define KH   8
#define DL   6
#define KNN  4
#define GG   32000
#define LMM  64
#define BL   (BB*LL)          // 2048
#define KE   (KH*EE)          // 2048
#define LK   (LL*KH)          // 4096
#define NXB  (GG/128)         // 250 logits col-blocks
#define NR   (BB*LMM*KNN)     // 1024 head rows

// plane sizes (elements per plane)
#define PXSA  ((long)BL*EE)
#define PXSAT ((long)BB*EE*LL)
#define PQ    ((long)BL*KE)
#define PP    ((long)BB*LK*LL)
#define PY    ((long)BL*KE)
#define PYD   ((long)BL*KE)
#define PWQA  ((long)DL*KE*EE)
#define PWDA  ((long)DL*KE*KE)
#define PWOA  ((long)DL*EE*KE)
#define PEMB  ((long)GG*EE)
#define PKC   ((long)KNN*EE*EE)
#define PWEM  ((long)EE*EE)
#define PLPT  ((long)BB*LMM*EE)
#define PXX1  ((long)BB*LMM*KNN*EE)
#define PTB   ((long)BB*LMM*KNN*LL)
#define PXX2  ((long)BB*LMM*KNN*EE)
#define PV    ((long)BB*LMM*KNN*EE)

// ---------------- static scratch -------------------------------------------
__device__ float g_z    [BL*EE];
__device__ float g_xsa  [BL*EE];
__device__ float g_xsad [BL*EE];
__device__ float g_tmp1 [BL*EE];
__device__ float g_tmp2 [BL*EE];
__device__ float g_xid  [4*BL*EE];                 // 4 split-K slabs
__device__ float g_h    [(long)BB*LK*LL];          // 32 MB fp32
__device__ float g_logits[(long)NR*GG];            // 131 MB
__device__ float g_lse  [NR];
__device__ float g_pmax [(long)NR*NXB];
__device__ float g_psum [(long)NR*NXB];

__device__ __nv_bfloat16 g_xsaP [2*PXSA];
__device__ __nv_bfloat16 g_xsaTP[2*PXSAT];
__device__ __nv_bfloat16 g_qP   [2*PQ];
__device__ __nv_bfloat16 g_pP   [2*PP];
__device__ __nv_bfloat16 g_yP   [2*PY];
__device__ __nv_bfloat16 g_ydP  [2*PYD];
__device__ __nv_bfloat16 g_wqP  [2*PWQA];
__device__ __nv_bfloat16 g_wdP  [2*PWDA];
__device__ __nv_bfloat16 g_woTP [2*PWOA];
__device__ __nv_bfloat16 g_embP [2*PEMB];
__device__ __nv_bfloat16 g_kcP  [2*PKC];
__device__ __nv_bfloat16 g_wemTP[2*PWEM];
__device__ __nv_bfloat16 g_lptP [2*PLPT];
__device__ __nv_bfloat16 g_xx1P [2*PXX1];
__device__ __nv_bfloat16 g_tbP  [2*PTB];
__device__ __nv_bfloat16 g_xx2P [2*PXX2];
__device__ __nv_bfloat16 g_vP   [2*PV];

// ---------------- mma.sync helpers -----------------------------------------
__device__ __forceinline__ uint32_t smem_u32(const void* p) {
    uint32_t a;
    asm("{ .reg .u64 t; cvta.to.shared.u64 t, %1; cvt.u32.u64 %0, t; }" : "=r"(a) : "l"(p));
    return a;
}
__device__ __forceinline__ void ldsm_x4(uint32_t* r, uint32_t addr) {
    asm volatile("ldmatrix.sync.aligned.m8n8.x4.shared.b16 {%0,%1,%2,%3}, [%4];"
        : "=r"(r[0]), "=r"(r[1]), "=r"(r[2]), "=r"(r[3]) : "r"(addr));
}
__device__ __forceinline__ void mma16816(float* c, const uint32_t* a, const uint32_t* b) {
    asm volatile("mma.sync.aligned.m16n8k16.row.col.f32.bf16.bf16.f32 "
        "{%0,%1,%2,%3}, {%4,%5,%6,%7}, {%8,%9}, {%0,%1,%2,%3};"
        : "+f"(c[0]), "+f"(c[1]), "+f"(c[2]), "+f"(c[3])
        : "r"(a[0]), "r"(a[1]), "r"(a[2]), "r"(a[3]), "r"(b[0]), "r"(b[1]));
}
#define CP_ASYNC(dst, src) \
    asm volatile("cp.async.ca.shared.global [%0], [%1], 16;" :: "r"(dst), "l"(src))
#define CP_COMMIT()  asm volatile("cp.async.commit_group;" ::: "memory")
#define CP_WAIT(n)   asm volatile("cp.async.wait_group %0;" :: "n"(n) : "memory")

// ---------------- tc_gemm ---------------------------------------------------
// 128x128 CTA tile, 256 threads, 4x2 warp grid, warp tile 32x64.
// K-tile = 64, 3-stage cp.async pipeline.
// splitK>1: blockIdx.z = chunk, writes slab Cf + chunk*sC (deterministic).
// pmax/psum non-null: fused per-CTA row max / sum-exp partials (for LSE).
#define LDT 72
#define TILE_B (128*LDT*2)
#define STAGE_B (4*TILE_B)
#define NSTAGE 3
#define TCSM (NSTAGE*STAGE_B)         // 221184
__global__ __launch_bounds__(256, 1) void tc_gemm(
    const __nv_bfloat16* __restrict__ Ah, const __nv_bfloat16* __restrict__ Al,
    const __nv_bfloat16* __restrict__ Bh, const __nv_bfloat16* __restrict__ Bl,
    const float* __restrict__ bias, float* __restrict__ Cf,
    __nv_bfloat16* __restrict__ Chi, __nv_bfloat16* __restrict__ Clo,
    float* __restrict__ pmax, float* __restrict__ psum, int nxb,
    int M, int N, int Kd, long sA, long sB, long sC, float alpha, int doRelu,
    int accFlag, int splitK, int kcTiles)
{
    extern __shared__ char smem[];
    int tid = threadIdx.x, lane = tid & 31, wid = tid >> 5;
    int wm = wid >> 1, wn = wid & 1;
    const int nbAll = Kd >> 6;
    long bz = blockIdx.z;
    int kb0 = 0, kbe = nbAll;
    if (splitK > 1) {
        int c = (int)bz; bz = 0;
        kb0 = c * kcTiles;
        kbe = min(nbAll, kb0 + kcTiles);
        if (Cf) Cf += (long)c * sC;        // slab per chunk
    } else {
        if (Cf) Cf += bz * sC;
    }
    Ah += bz * sA; Al += bz * sA; Bh += bz * sB; Bl += bz * sB;
    if (Chi) { Chi += bz * sC; Clo += bz * sC; }
    int m0 = blockIdx.y * 128, n0 = blockIdx.x * 128;

    const __nv_bfloat16* srcs[4] = { Ah + (long)m0 * Kd, Al + (long)m0 * Kd,
                                     Bh + (long)n0 * Kd, Bl + (long)n0 * Kd };

    auto load_blk = [&](int kb, int st) {
        char* base = smem + st * STAGE_B;
        #pragma unroll
        for (int tI = 0; tI < 4; tI++) {
            const __nv_bfloat16* s = srcs[tI] + (long)kb * 64;
            char* d = base + tI * TILE_B;
            #pragma unroll
            for (int i = 0; i < 4; i++) {
                int idx = tid + i * 256;
                int row = idx >> 3, cb = (idx & 7) * 16;
                uint32_t daddr = smem_u32(d + row * (LDT * 2) + cb);
                CP_ASYNC(daddr, (const char*)(s + (long)row * Kd) + cb);
            }
        }
        CP_COMMIT();
    };

    float acc[2][8][4];
    #pragma unroll
    for (int a = 0; a < 2; a++)
        #pragma unroll
        for (int b = 0; b < 8; b++)
            #pragma unroll
            for (int c = 0; c < 4; c++) acc[a][b][c] = 0.f;

    const int nb = kbe - kb0;
    load_blk(kb0, 0);
    if (nb > 1) load_blk(kb0 + 1, 1);

    for (int t = 0; t < nb; t++) {
        int st = t % NSTAGE;
        if (t + 1 < nb) CP_WAIT(1); else CP_WAIT(0);
        __syncthreads();
        if (t + 2 < nb) load_blk(kb0 + t + 2, (t + 2) % NSTAGE);

        char* base = smem + st * STAGE_B;
        uint32_t baseAh = smem_u32(base);
        uint32_t baseAl = baseAh + TILE_B;
        uint32_t baseBh = baseAh + 2 * TILE_B;
        uint32_t baseBl = baseAh + 3 * TILE_B;

        #pragma unroll
        for (int ks = 0; ks < 4; ks++) {
            uint32_t ah[2][4], al[2][4];
            int arow = wm * 32 + (lane & 15);
            int acb  = ks * 32 + (lane >> 4) * 16;
            #pragma unroll
            for (int tm = 0; tm < 2; tm++) {
                uint32_t off = (arow + tm * 16) * (LDT * 2) + acb;
                ldsm_x4(ah[tm], baseAh + off);
                ldsm_x4(al[tm], baseAl + off);
            }
            uint32_t bh[8][2], bl[8][2];
            int q = lane >> 3;
            int brow_base = wn * 64 + ((q & 2) ? 8 : 0) + (lane & 7);
            int bcb = ks * 32 + (q & 1) * 16;
            #pragma unroll
            for (int p = 0; p < 4; p++) {
                uint32_t off = (brow_base + p * 16) * (LDT * 2) + bcb;
                uint32_t r[4];
                ldsm_x4(r, baseBh + off);
                bh[2*p][0] = r[0]; bh[2*p][1] = r[1]; bh[2*p+1][0] = r[2]; bh[2*p+1][1] = r[3];
                ldsm_x4(r, baseBl + off);
                bl[2*p][0] = r[0]; bl[2*p][1] = r[1]; bl[2*p+1][0] = r[2]; bl[2*p+1][1] = r[3];
            }
            #pragma unroll
            for (int tm = 0; tm < 2; tm++)
                #pragma unroll
                for (int tn = 0; tn < 8; tn++) {
                    mma16816(acc[tm][tn], ah[tm], bh[tn]);
                    mma16816(acc[tm][tn], ah[tm], bl[tn]);
                    mma16816(acc[tm][tn], al[tm], bh[tn]);
                }
        }
    }
    __syncthreads();

    #pragma unroll
    for (int tm = 0; tm < 2; tm++) {
        #pragma unroll
        for (int half = 0; half < 2; half++) {
            int m = m0 + wm * 32 + tm * 16 + (lane >> 2) + half * 8;
            #pragma unroll
            for (int tn = 0; tn < 8; tn++) {
                int n = n0 + wn * 64 + tn * 8 + (lane & 3) * 2;
                float v0 = alpha * acc[tm][tn][half * 2 + 0];
                float v1 = alpha * acc[tm][tn][half * 2 + 1];
                if (bias) { v0 += bias[n]; v1 += bias[n + 1]; }
                if (doRelu) { v0 = fmaxf(v0, 0.f); v1 = fmaxf(v1, 0.f); }
                long idx = (long)m * N + n;
                if (Cf) {
                    if (accFlag) { Cf[idx] += v0; Cf[idx + 1] += v1; }
                    else { Cf[idx] = v0; Cf[idx + 1] = v1; }
                } else {
                    __nv_bfloat16 h0 = __float2bfloat16(v0);
                    __nv_bfloat16 h1 = __float2bfloat16(v1);
                    __nv_bfloat162 hp; hp.x = h0; hp.y = h1;
                    *reinterpret_cast<__nv_bfloat162*>(&Chi[idx]) = hp;
                    __nv_bfloat162 lp;
                    lp.x = __float2bfloat16(v0 - __bfloat162float(h0));
                    lp.y = __float2bfloat16(v1 - __bfloat162float(h1));
                    *reinterpret_cast<__nv_bfloat162*>(&Clo[idx]) = lp;
                }
            }
        }
    }

    // fused per-CTA row-max / sum-exp partials (LSE)
    if (pmax) {
        float* sm8 = (float*)smem;                    // [128][8]
        float* rowred = (float*)(smem + 128 * 8 * 4); // [128]
        int slot = wn * 4 + (lane & 3);
        __syncthreads();
        #pragma unroll
        for (int tm = 0; tm < 2; tm++)
            #pragma unroll
            for (int half = 0; half < 2; half++) {
                int rl = wm * 32 + tm * 16 + (lane >> 2) + half * 8;
                float lm = -1e30f;
                #pragma unroll
                for (int tn = 0; tn < 8; tn++)
                    #pragma unroll
                    for (int e = 0; e < 2; e++)
                        lm = fmaxf(lm, alpha * acc[tm][tn][half * 2 + e]);
                sm8[rl * 8 + slot] = lm;
            }
        __syncthreads();
        if (tid < 128) {
            float mR = -1e30f;
            #pragma unroll
            for (int i = 0; i < 8; i++) mR = fmaxf(mR, sm8[tid * 8 + i]);
            rowred[tid] = mR;
        }
        __syncthreads();
        #pragma unroll
        for (int tm = 0; tm < 2; tm++)
            #pragma unroll
            for (int half = 0; half < 2; half++) {
                int rl = wm * 32 + tm * 16 + (lane >> 2) + half * 8;
                float rm = rowred[rl];
                float ls = 0.f;
                #pragma unroll
                for (int tn = 0; tn < 8; tn++)
                    #pragma unroll
                    for (int e = 0; e < 2; e++)
                        ls += expf(alpha * acc[tm][tn][half * 2 + e] - rm);
                sm8[rl * 8 + slot] = ls;
            }
        __syncthreads();
        if (tid < 128) {
            float sR = 0.f;
            #pragma unroll
            for (int i = 0; i < 8; i++) sR += sm8[tid * 8 + i];
            long r = m0 + tid;
            pmax[r * nxb + blockIdx.x] = rowred[tid];
            psum[r * nxb + blockIdx.x] = sR;
        }
    }
}

// ---------------- SIMT 64x64 tile core (small fp32 GEMMs) ------------------
__device__ __forceinline__ void gemm64_acc(
    const float* __restrict__ A, const float* __restrict__ Bm, bool transB,
    int N, int Kd, int m0, int n0, int rollL, int rollOff,
    float As[32][64], float Bs[32][64], float acc[4][4])
{
    int tid = threadIdx.x;
    int tx = tid & 15, ty = tid >> 4;
    int arow = tid >> 2, ak0 = (tid & 3) * 8;
    int gm = m0 + arow;
    if (rollL) {
        int g = gm / rollL, l = gm - g * rollL;
        l += rollOff; if (l >= rollL) l -= rollL;
        gm = g * rollL + l;
    }
    const float* Aptr = A + (long)gm * Kd + ak0;
    for (int k0 = 0; k0 < Kd; k0 += 32) {
        #pragma unroll
        for (int i = 0; i < 8; i += 4) {
            float4 v = *(const float4*)(Aptr + k0 + i);
            As[ak0+i+0][arow] = v.x; As[ak0+i+1][arow] = v.y;
            As[ak0+i+2][arow] = v.z; As[ak0+i+3][arow] = v.w;
        }
        if (transB) {
            int br = tid >> 2, bk0 = (tid & 3) * 8;
            const float* Bp = Bm + (long)(n0 + br) * Kd + k0 + bk0;
            #pragma unroll
            for (int i = 0; i < 8; i += 4) {
                float4 v = *(const float4*)(Bp + i);
                Bs[bk0+i+0][br] = v.x; Bs[bk0+i+1][br] = v.y;
                Bs[bk0+i+2][br] = v.z; Bs[bk0+i+3][br] = v.w;
            }
        } else {
            int bk = tid >> 3, bn0 = (tid & 7) * 8;
            const float* Bp = Bm + (long)(k0 + bk) * N + n0 + bn0;
            #pragma unroll
            for (int i = 0; i < 8; i += 4)
                *(float4*)&Bs[bk][bn0 + i] = *(const float4*)(Bp + i);
        }
        __syncthreads();
        #pragma unroll
        for (int k = 0; k < 32; k++) {
            float a[4], b[4];
            *(float4*)a = *(const float4*)&As[k][ty * 4];
            *(float4*)b = *(const float4*)&Bs[k][tx * 4];
            #pragma unroll
            for (int i = 0; i < 4; i++)
                #pragma unroll
                for (int j = 0; j < 4; j++)
                    acc[i][j] += a[i] * b[j];
        }
        __syncthreads();
    }
}

// pair_k: z=0: tmp1 = relu(roll(xsa,+1) @ wt); z=1: tmp2 = relu(roll(xsa,-1) @ wtc^T)
__global__ __launch_bounds__(256) void pair_k(
    const float* __restrict__ xsa, const float* __restrict__ wt,
    const float* __restrict__ wtc, float* __restrict__ tmp1, float* __restrict__ tmp2)
{
    __shared__ float As[32][64];
    __shared__ float Bs[32][64];
    int m0 = blockIdx.y * 64, n0 = blockIdx.x * 64;
    float acc[4][4] = {};
    float* C;
    if (blockIdx.z == 0) {
        gemm64_acc(xsa, wt, false, EE, EE, m0, n0, LL, LL - 1, As, Bs, acc);
        C = tmp1;
    } else {
        gemm64_acc(xsa, wtc, true, EE, EE, m0, n0, LL, 1, As, Bs, acc);
        C = tmp2;
    }
    int tid = threadIdx.x, tx = tid & 15, ty = tid >> 4;
    #pragma unroll
    for (int i = 0; i < 4; i++) {
        int m = m0 + ty * 4 + i;
        #pragma unroll
        for (int j = 0; j < 4; j++) {
            int n = n0 + tx * 4 + j;
            C[(long)m * EE + n] = fmaxf(acc[i][j], 0.f);
        }
    }
}

// sum3_k: xsad = tmp1 @ wtc + tmp2 @ wt^T + z @ wu^T + bt
__global__ __launch_bounds__(256) void sum3_k(
    const float* __restrict__ tmp1, const float* __restrict__ tmp2,
    const float* __restrict__ z, const float* __restrict__ wt,
    const float* __restrict__ wtc, const float* __restrict__ wu,
    const float* __restrict__ bt, float* __restrict__ xsad)
{
    __shared__ float As[32][64];
    __shared__ float Bs[32][64];
    int m0 = blockIdx.y * 64, n0 = blockIdx.x * 64;
    float acc[4][4] = {};
    gemm64_acc(tmp1, wtc, false, EE, EE, m0, n0, 0, 0, As, Bs, acc);
    gemm64_acc(tmp2, wt,  true,  EE, EE, m0, n0, 0, 0, As, Bs, acc);
    gemm64_acc(z,    wu,  true,  EE, EE, m0, n0, 0, 0, As, Bs, acc);
    int tid = threadIdx.x, tx = tid & 15, ty = tid >> 4;
    #pragma unroll
    for (int i = 0; i < 4; i++) {
        int m = m0 + ty * 4 + i;
        #pragma unroll
        for (int j = 0; j < 4; j++) {
            int n = n0 + tx * 4 + j;
            xsad[(long)m * EE + n] = acc[i][j] + bt[n];
        }
    }
}

// ---------------- split / transpose-split ----------------------------------
__global__ void split_k(const float* __restrict__ s, __nv_bfloat16* __restrict__ h,
                        __nv_bfloat16* __restrict__ l, long n)
{
    long i = blockIdx.x * 256L + threadIdx.x;
    if (i < n) {
        float v = s[i];
        __nv_bfloat16 a = __float2bfloat16(v);
        h[i] = a;
        l[i] = __float2bfloat16(v - __bfloat162float(a));
    }
}
__global__ void tsplit_k(const float* __restrict__ s, __nv_bfloat16* __restrict__ h,
                         __nv_bfloat16* __restrict__ l, int R, int C, long sS, long sD)
{
    __shared__ float t[32][33];
    int b = blockIdx.z;
    s += (long)b * sS; h += (long)b * sD; l += (long)b * sD;
    int r0 = blockIdx.y * 32, c0 = blockIdx.x * 32;
    int x = threadIdx.x, y = threadIdx.y;
    #pragma unroll
    for (int i = 0; i < 32; i += 8) t[y + i][x] = s[(long)(r0 + y + i) * C + c0 + x];
    __syncthreads();
    #pragma unroll
    for (int i = 0; i < 32; i += 8) {
        float v = t[x][y + i];
        __nv_bfloat16 a = __float2bfloat16(v);
        long idx = (long)(c0 + y + i) * R + r0 + x;
        h[idx] = a;
        l[idx] = __float2bfloat16(v - __bfloat162float(a));
    }
}

// ---------------- elementwise / reduction kernels --------------------------
__device__ __forceinline__ float blkSum256(float v) {
    __shared__ float sh[8];
    int lane = threadIdx.x & 31, w = threadIdx.x >> 5;
    #pragma unroll
    for (int o = 16; o; o >>= 1) v += __shfl_xor_sync(0xffffffffu, v, o);
    __syncthreads();
    if (lane == 0) sh[w] = v;
    __syncthreads();
    float r = sh[0];
    #pragma unroll
    for (int i = 1; i < 8; i++) r += sh[i];
    return r;
}
__device__ __forceinline__ float blkMax256(float v) {
    __shared__ float sh[8];
    int lane = threadIdx.x & 31, w = threadIdx.x >> 5;
    #pragma unroll
    for (int o = 16; o; o >>= 1) v = fmaxf(v, __shfl_xor_sync(0xffffffffu, v, o));
    __syncthreads();
    if (lane == 0) sh[w] = v;
    __syncthreads();
    float r = sh[0];
    #pragma unroll
    for (int i = 1; i < 8; i++) r = fmaxf(r, sh[i]);
    return r;
}
__device__ __forceinline__ void emit_planes(__nv_bfloat16* h, __nv_bfloat16* l,
                                            long idx, float v) {
    __nv_bfloat16 a = __float2bfloat16(v);
    h[idx] = a;
    l[idx] = __float2bfloat16(v - __bfloat162float(a));
}

__global__ void embed_norm_k(const int* __restrict__ masked, const float* __restrict__ embed,
                             float* __restrict__ z, float* __restrict__ xsa,
                             __nv_bfloat16* __restrict__ xh, __nv_bfloat16* __restrict__ xl)
{
    long row = blockIdx.x; int t = threadIdx.x;
    float v = embed[(long)masked[row] * EE + t];
    float mean = blkSum256(v) * (1.f / EE);
    float d = v - mean;
    float var = fmaxf(blkSum256(d * d) * (1.f / (EE - 1)), 0.f);
    float o = v / (1.f + sqrtf(var));
    long i = row * EE + t;
    z[i] = o;
    xsa[i] = o;
    emit_planes(xh, xl, i, o);
}

__global__ void softmax512_k(const float* __restrict__ h,
                             __nv_bfloat16* __restrict__ ph, __nv_bfloat16* __restrict__ pl)
{
    long row = blockIdx.x;
    const float* p = h + row * 512;
    int t = threadIdx.x;
    float a = p[t], b = p[t + 256];
    float m = blkMax256(fmaxf(a, b));
    float ea = __expf(a - m), eb = __expf(b - m);
    float s = blkSum256(ea + eb);
    float inv = 1.f / s;
    emit_planes(ph, pl, row * 512 + t, ea * inv);
    emit_planes(ph, pl, row * 512 + t + 256, eb * inv);
}

__global__ void update_k(const float* __restrict__ xsad, const float* __restrict__ xid,
                         float* __restrict__ xsa,
                         __nv_bfloat16* __restrict__ xh, __nv_bfloat16* __restrict__ xl)
{
    long row = blockIdx.x; int t = threadIdx.x;
    long i = row * EE + t;
    const long S = (long)BL * EE;
    float s = xsad[i] + ((xid[i] + xid[i + S]) + (xid[i + 2 * S] + xid[i + 3 * S]));
    float mean = blkSum256(s) * (1.f / EE);
    float d = s - mean;
    float var = fmaxf(blkSum256(d * d) * (1.f / (EE - 1)), 0.f);
    float a = s / (1.f + sqrtf(var));
    float x = xsa[i] + 0.05f * a;
    float mean2 = blkSum256(x) * (1.f / EE);
    float d2 = x - mean2;
    float var2 = fmaxf(blkSum256(d2 * d2) * (1.f / (EE - 1)), 0.f);
    float o = x / (1.f + sqrtf(var2));
    xsa[i] = o;
    emit_planes(xh, xl, i, o);
}

__global__ void gather_lptok_k(const float* __restrict__ xsa, const int* __restrict__ mask,
                               __nv_bfloat16* __restrict__ h, __nv_bfloat16* __restrict__ l)
{
    int r = blockIdx.x;
    int b = r / LMM, lm = r % LMM;
    int pos = mask[b * LMM + lm];
    int t = threadIdx.x;
    float v = xsa[((long)b * LL + pos) * EE + t];
    emit_planes(h, l, (long)r * EE + t, v);
}

__global__ void lse_reduce_k(const float* __restrict__ pmax, const float* __restrict__ psum,
                             float* __restrict__ lse)
{
    long row = blockIdx.x;
    int t = threadIdx.x;
    const float* pm = pmax + row * NXB;
    const float* ps = psum + row * NXB;
    float m = -1e30f;
    for (int i = t; i < NXB; i += 256) m = fmaxf(m, pm[i]);
    m = blkMax256(m);
    float s = 0.f;
    for (int i = t; i < NXB; i += 256) s += ps[i] * expf(pm[i] - m);
    s = blkSum256(s);
    if (!t) lse[row] = m + logf(s);
}

__global__ void final_k(const float* __restrict__ logits, const float* __restrict__ lse,
                        const int* __restrict__ unmasked, const int* __restrict__ mask,
                        float* __restrict__ out)
{
    int b = blockIdx.x, lm = threadIdx.x;
    int pos = mask[b * LMM + lm];
    int tgt = unmasked[b * LL + pos];
    float v[KNN]; float m = -1e30f;
    #pragma unroll
    for (int kn = 0; kn < KNN; kn++) {
        int n = b * (LMM * KNN) + lm * KNN + kn;
        v[kn] = logits[(long)n * GG + tgt] - lse[n];
        m = fmaxf(m, v[kn]);
    }
    float s = 0.f;
    #pragma unroll
    for (int kn = 0; kn < KNN; kn++) s += expf(v[kn] - m);
    float cent = m + logf(s) - logf((float)KNN);
    __shared__ float sh[LMM];
    sh[lm] = cent; __syncthreads();
    for (int o = 32; o; o >>= 1) { if (lm < o) sh[lm] += sh[lm + o]; __syncthreads(); }
    if (!lm) out[b] = -sh[0] / (float)LMM;
}

// ---------------- host orchestration ---------------------------------------
typedef __nv_bfloat16 bf;
template <typename T> static inline T* sym(const void* s) {
    void* p = nullptr; cudaGetSymbolAddress(&p, s); return (T*)p;
}
static inline void tc(cudaStream_t st, const bf* Ah, const bf* Al, const bf* Bh, const bf* Bl,
                      const float* bias, float* Cf, bf* Ch, bf* Cl,
                      int M, int N, int K, long sA, long sB, long sC, int batch,
                      float alpha, int relu, int accF = 0, int splitK = 1,
                      float* pmax = nullptr, float* psum = nullptr)
{
    int kcT = 1;
    int zdim = batch;
    if (splitK > 1) {
        int nbAll = K >> 6;
        kcT = (nbAll + splitK - 1) / splitK;
        zdim = splitK;
    }
    dim3 g(N / 128, M / 128, zdim);
    tc_gemm<<<g, 256, TCSM, st>>>(Ah, Al, Bh, Bl, bias, Cf, Ch, Cl, pmax, psum, N / 128,
                                  M, N, K, sA, sB, sC, alpha, relu, accF, splitK, kcT);
}

extern "C" void kernel_launch(void* const* d_in, const int* in_sizes, int n_in,
                              void* d_out, int out_size)
{
    const int*   masked   = (const int*)  d_in[0];
    const int*   unmasked = (const int*)  d_in[1];
    const int*   mask     = (const int*)  d_in[2];
    const float* embed    = (const float*)d_in[3];
    const float* Wt       = (const float*)d_in[4];
    const float* bt       = (const float*)d_in[5];
    const float* Wtc      = (const float*)d_in[6];
    const float* Wq       = (const float*)d_in[7];
    const float* Wd       = (const float*)d_in[8];
    const float* Wo       = (const float*)d_in[9];
    const float* Wu       = (const float*)d_in[10];
    const float* Wem      = (const float*)d_in[11];
    const float* Wkc      = (const float*)d_in[12];
    const float* bkc      = (const float*)d_in[13];
    float* out = (float*)d_out;

    static bool inited = false;
    static cudaStream_t s2 = nullptr;
    static cudaEvent_t evFork = nullptr, evS = nullptr;
    if (!inited) {
        cudaFuncSetAttribute(tc_gemm, cudaFuncAttributeMaxDynamicSharedMemorySize, TCSM);
        cudaStreamCreateWithFlags(&s2, cudaStreamNonBlocking);
        cudaEventCreateWithFlags(&evFork, cudaEventDisableTiming);
        cudaEventCreateWithFlags(&evS, cudaEventDisableTiming);
        inited = true;
    }
    cudaStream_t s0 = 0;

    float *z = sym<float>(g_z), *xsa = sym<float>(g_xsa), *xsad = sym<float>(g_xsad);
    float *tmp1 = sym<float>(g_tmp1), *tmp2 = sym<float>(g_tmp2), *xid = sym<float>(g_xid);
    float *h = sym<float>(g_h), *logits = sym<float>(g_logits), *lse = sym<float>(g_lse);
    float *pmax = sym<float>(g_pmax), *psum = sym<float>(g_psum);
    bf *xsaP = sym<bf>(g_xsaP), *xsaTP = sym<bf>(g_xsaTP);
    bf *qP = sym<bf>(g_qP), *pP = sym<bf>(g_pP), *yP = sym<bf>(g_yP), *ydP = sym<bf>(g_ydP);
    bf *wqP = sym<bf>(g_wqP), *wdP = sym<bf>(g_wdP), *woTP = sym<bf>(g_woTP);
    bf *embP = sym<bf>(g_embP), *kcP = sym<bf>(g_kcP), *wemTP = sym<bf>(g_wemTP);
    bf *lptP = sym<bf>(g_lptP), *xx1P = sym<bf>(g_xx1P), *tbP = sym<bf>(g_tbP);
    bf *xx2P = sym<bf>(g_xx2P), *vP = sym<bf>(g_vP);

    embed_norm_k<<<BL, 256, 0, s0>>>(masked, embed, z, xsa, xsaP, xsaP + PXSA);
    split_k<<<(PWQA + 255) / 256, 256, 0, s0>>>(Wq, wqP, wqP + PWQA, PWQA);

    for (int d = 0; d < DL; d++) {
        const float* wt  = Wt  + (long)d * EE * EE;
        const float* btd = bt  + (long)d * EE;
        const float* wtc = Wtc + (long)d * EE * EE;
        const float* wu  = Wu  + (long)d * EE * EE;
        const bf* wqh = wqP + (long)d * KE * EE;  const bf* wql = wqh + PWQA;
        const bf* wdh = wdP + (long)d * KE * KE;  const bf* wdl = wdh + PWDA;
        const bf* woh = woTP + (long)d * EE * KE; const bf* wol = woh + PWOA;

        cudaEventRecord(evFork, s0);
        cudaStreamWaitEvent(s2, evFork, 0);
        if (d == 0) {
            split_k<<<(PWDA + 255) / 256, 256, 0, s2>>>(Wd, wdP, wdP + PWDA, PWDA);
            split_k<<<(PEMB + 255) / 256, 256, 0, s2>>>(embed, embP, embP + PEMB, PEMB);
            split_k<<<(PKC + 255) / 256, 256, 0, s2>>>(Wkc, kcP, kcP + PKC, PKC);
            { dim3 b(32, 8), g(EE / 32, KE / 32, DL);
              tsplit_k<<<g, b, 0, s2>>>(Wo, woTP, woTP + PWOA, KE, EE, (long)KE * EE, (long)EE * KE); }
            { dim3 b(32, 8), g(EE / 32, EE / 32, 1);
              tsplit_k<<<g, b, 0, s2>>>(Wem, wemTP, wemTP + PWEM, EE, EE, 0, 0); }
        }
        { dim3 b(32, 8), g(EE / 32, LL / 32, BB);
          tsplit_k<<<g, b, 0, s2>>>(xsa, xsaTP, xsaTP + PXSAT, LL, EE, (long)LL * EE, (long)EE * LL); }
        { dim3 g(EE / 64, BL / 64, 2);
          pair_k<<<g, 256, 0, s2>>>(xsa, wt, wtc, tmp1, tmp2); }
        { dim3 g(EE / 64, BL / 64, 1);
          sum3_k<<<g, 256, 0, s2>>>(tmp1, tmp2, z, wt, wtc, wu, btd, xsad); }
        cudaEventRecord(evS, s2);

        tc(s0, xsaP, xsaP + PXSA, wqh, wql, nullptr, nullptr, qP, qP + PQ,
           BL, KE, EE, 0, 0, 0, 1, 1.f, 0);
        tc(s0, qP, qP + PQ, xsaP, xsaP + PXSA, nullptr, h, nullptr, nullptr,
           LK, LL, EE, (long)LK * EE, (long)LL * EE, (long)LK * LL, BB, 1.f / 16.f, 0);
        softmax512_k<<<BB * LK, 256, 0, s0>>>(h, pP, pP + PP);

        cudaStreamWaitEvent(s0, evS, 0);

        tc(s0, pP, pP + PP, xsaTP, xsaTP + PXSAT, nullptr, nullptr, yP, yP + PY,
           LK, EE, LL, (long)LK * LL, (long)EE * LL, (long)LK * EE, BB, 1.f, 0);
        tc(s0, yP, yP + PY, wdh, wdl, nullptr, nullptr, ydP, ydP + PYD,
           BL, KE, KE, 0, 0, 0, 1, 1.f, 1);
        // xid = yd @ wo — deterministic split-K=4 into 4 slabs (stride BL*EE)
        tc(s0, ydP, ydP + PYD, woh, wol, nullptr, xid, nullptr, nullptr,
           BL, EE, KE, 0, 0, (long)BL * EE, 1, 1.f, 0, 0, /*splitK=*/4);
        update_k<<<BL, 256, 0, s0>>>(xsad, xid, xsa, xsaP, xsaP + PXSA);
    }

    // ---- head ----
    // fork: xsaT transpose (needed only by xx2) runs on s2 alongside gather/xx1/tb
    cudaEventRecord(evFork, s0);
    cudaStreamWaitEvent(s2, evFork, 0);
    { dim3 b(32, 8), g(EE / 32, LL / 32, BB);
      tsplit_k<<<g, b, 0, s2>>>(xsa, xsaTP, xsaTP + PXSAT, LL, EE, (long)LL * EE, (long)EE * LL); }
    cudaEventRecord(evS, s2);

    gather_lptok_k<<<BB * LMM, 256, 0, s0>>>(xsa, mask, lptP, lptP + PLPT);
    tc(s0, lptP, lptP + PLPT, kcP, kcP + PKC, bkc, nullptr, xx1P, xx1P + PXX1,
       BB * LMM, KNN * EE, EE, 0, 0, 0, 1, 1.f, 0);
    tc(s0, xx1P, xx1P + PXX1, xsaP, xsaP + PXSA, nullptr, nullptr, tbP, tbP + PTB,
       LMM * KNN, LL, EE, (long)LMM * KNN * EE, (long)LL * EE, (long)LMM * KNN * LL, BB, 1.f, 0);
    cudaStreamWaitEvent(s0, evS, 0);
    tc(s0, tbP, tbP + PTB, xsaTP, xsaTP + PXSAT, nullptr, nullptr, xx2P, xx2P + PXX2,
       LMM * KNN, EE, LL, (long)LMM * KNN * LL, (long)EE * LL, (long)LMM * KNN * EE, BB, 1.f, 0);
    tc(s0, xx2P, xx2P + PXX2, wemTP, wemTP + PWEM, nullptr, nullptr, vP, vP + PV,
       BB * LMM * KNN, EE, EE, 0, 0, 0, 1, 1.f, 0);
    // logits GEMM with fused partial LSE
    tc(s0, vP, vP + PV, embP, embP + PEMB, nullptr, logits, nullptr, nullptr,
       NR, GG, EE, 0, 0, 0, 1, 1.f, 0, 0, 1, pmax, psum);
    lse_reduce_k<<<NR, 256, 0, s0>>>(pmax, psum, lse);
    final_k<<<BB, LMM, 0, s0>>>(logits, lse, unmasked, mask, out);
}

// round 16
// speedup vs baseline: 1.0283x; 1.0132x over previous
#include <cuda_runtime.h>
#include <cuda_bf16.h>
#include <math.h>
#include <stdint.h>

#define BB   4
#define LL   512
#define EE   256
#define KH   8
#define DL   6
#define KNN  4
#define GG   32000
#define LMM  64
#define BL   (BB*LL)          // 2048
#define KE   (KH*EE)          // 2048
#define LK   (LL*KH)          // 4096
#define NXB  (GG/128)         // 250 logits col-blocks
#define NR   (BB*LMM*KNN)     // 1024 head rows

// plane sizes (elements per plane)
#define PXSA  ((long)BL*EE)
#define PXSAT ((long)BB*EE*LL)
#define PQ    ((long)BL*KE)
#define PP    ((long)BB*LK*LL)
#define PY    ((long)BL*KE)
#define PYD   ((long)BL*KE)
#define PWQA  ((long)DL*KE*EE)
#define PWDA  ((long)DL*KE*KE)
#define PWOA  ((long)DL*EE*KE)
#define PEMB  ((long)GG*EE)
#define PKC   ((long)KNN*EE*EE)
#define PWEM  ((long)EE*EE)
#define PLPT  ((long)BB*LMM*EE)
#define PXX1  ((long)BB*LMM*KNN*EE)
#define PTB   ((long)BB*LMM*KNN*LL)
#define PXX2  ((long)BB*LMM*KNN*EE)
#define PV    ((long)BB*LMM*KNN*EE)

// ---------------- static scratch -------------------------------------------
__device__ float g_z    [BL*EE];
__device__ float g_xsa  [BL*EE];
__device__ float g_xsad [BL*EE];
__device__ float g_tmp1 [BL*EE];
__device__ float g_tmp2 [BL*EE];
__device__ float g_xid  [4*BL*EE];                 // 4 split-K slabs
__device__ float g_h    [(long)BB*LK*LL];          // 32 MB fp32
__device__ float g_logits[(long)NR*GG];            // 131 MB
__device__ float g_lse  [NR];
__device__ float g_pmax [(long)NR*NXB];
__device__ float g_psum [(long)NR*NXB];

__device__ __nv_bfloat16 g_xsaP [2*PXSA];
__device__ __nv_bfloat16 g_xsaTP[2*PXSAT];
__device__ __nv_bfloat16 g_qP   [2*PQ];
__device__ __nv_bfloat16 g_pP   [PP];              // hi plane only
__device__ __nv_bfloat16 g_yP   [2*PY];
__device__ __nv_bfloat16 g_ydP  [2*PYD];
__device__ __nv_bfloat16 g_wqP  [2*PWQA];
__device__ __nv_bfloat16 g_wdP  [2*PWDA];
__device__ __nv_bfloat16 g_woTP [2*PWOA];
__device__ __nv_bfloat16 g_embP [2*PEMB];
__device__ __nv_bfloat16 g_kcP  [2*PKC];
__device__ __nv_bfloat16 g_wemTP[2*PWEM];
__device__ __nv_bfloat16 g_lptP [2*PLPT];
__device__ __nv_bfloat16 g_xx1P [2*PXX1];
__device__ __nv_bfloat16 g_tbP  [2*PTB];
__device__ __nv_bfloat16 g_xx2P [2*PXX2];
__device__ __nv_bfloat16 g_vP   [2*PV];

// ---------------- mma.sync helpers -----------------------------------------
__device__ __forceinline__ uint32_t smem_u32(const void* p) {
    uint32_t a;
    asm("{ .reg .u64 t; cvta.to.shared.u64 t, %1; cvt.u32.u64 %0, t; }" : "=r"(a) : "l"(p));
    return a;
}
__device__ __forceinline__ void ldsm_x4(uint32_t* r, uint32_t addr) {
    asm volatile("ldmatrix.sync.aligned.m8n8.x4.shared.b16 {%0,%1,%2,%3}, [%4];"
        : "=r"(r[0]), "=r"(r[1]), "=r"(r[2]), "=r"(r[3]) : "r"(addr));
}
__device__ __forceinline__ void mma16816(float* c, const uint32_t* a, const uint32_t* b) {
    asm volatile("mma.sync.aligned.m16n8k16.row.col.f32.bf16.bf16.f32 "
        "{%0,%1,%2,%3}, {%4,%5,%6,%7}, {%8,%9}, {%0,%1,%2,%3};"
        : "+f"(c[0]), "+f"(c[1]), "+f"(c[2]), "+f"(c[3])
        : "r"(a[0]), "r"(a[1]), "r"(a[2]), "r"(a[3]), "r"(b[0]), "r"(b[1]));
}
#define CP_ASYNC(dst, src) \
    asm volatile("cp.async.ca.shared.global [%0], [%1], 16;" :: "r"(dst), "l"(src))
#define CP_COMMIT()  asm volatile("cp.async.commit_group;" ::: "memory")
#define CP_WAIT(n)   asm volatile("cp.async.wait_group %0;" :: "n"(n) : "memory")

// ---------------- tc_gemm ---------------------------------------------------
// 128x128 CTA tile, 256 threads, 4x2 warp grid, warp tile 32x64.
// K-tile = 64, 3-stage cp.async pipeline.
// nProd==3: acc = Ah*Bh + Ah*Bl + Al*Bh  (fp32-emulating)
// nProd==2: acc = Ah*Bh + Ah*Bl          (A lo-plane ignored, not loaded)
// splitK>1: blockIdx.z = chunk, writes slab Cf + chunk*sC (deterministic).
// pmax/psum non-null: fused per-CTA row max / sum-exp partials (for LSE).
#define LDT 72
#define TILE_B (128*LDT*2)
#define STAGE_B (4*TILE_B)
#define NSTAGE 3
#define TCSM (NSTAGE*STAGE_B)         // 221184
__global__ __launch_bounds__(256, 1) void tc_gemm(
    const __nv_bfloat16* __restrict__ Ah, const __nv_bfloat16* __restrict__ Al,
    const __nv_bfloat16* __restrict__ Bh, const __nv_bfloat16* __restrict__ Bl,
    const float* __restrict__ bias, float* __restrict__ Cf,
    __nv_bfloat16* __restrict__ Chi, __nv_bfloat16* __restrict__ Clo,
    float* __restrict__ pmax, float* __restrict__ psum, int nxb,
    int M, int N, int Kd, long sA, long sB, long sC, float alpha, int doRelu,
    int accFlag, int splitK, int kcTiles, int nProd)
{
    extern __shared__ char smem[];
    int tid = threadIdx.x, lane = tid & 31, wid = tid >> 5;
    int wm = wid >> 1, wn = wid & 1;
    const int nbAll = Kd >> 6;
    long bz = blockIdx.z;
    int kb0 = 0, kbe = nbAll;
    if (splitK > 1) {
        int c = (int)bz; bz = 0;
        kb0 = c * kcTiles;
        kbe = min(nbAll, kb0 + kcTiles);
        if (Cf) Cf += (long)c * sC;        // slab per chunk
    } else {
        if (Cf) Cf += bz * sC;
    }
    Ah += bz * sA; Al += bz * sA; Bh += bz * sB; Bl += bz * sB;
    if (Chi) { Chi += bz * sC; Clo += bz * sC; }
    int m0 = blockIdx.y * 128, n0 = blockIdx.x * 128;

    const __nv_bfloat16* srcs[4] = { Ah + (long)m0 * Kd, Al + (long)m0 * Kd,
                                     Bh + (long)n0 * Kd, Bl + (long)n0 * Kd };

    auto load_blk = [&](int kb, int st) {
        char* base = smem + st * STAGE_B;
        #pragma unroll
        for (int tI = 0; tI < 4; tI++) {
            if (tI == 1 && nProd == 2) continue;     // skip A lo plane
            const __nv_bfloat16* s = srcs[tI] + (long)kb * 64;
            char* d = base + tI * TILE_B;
            #pragma unroll
            for (int i = 0; i < 4; i++) {
                int idx = tid + i * 256;
                int row = idx >> 3, cb = (idx & 7) * 16;
                uint32_t daddr = smem_u32(d + row * (LDT * 2) + cb);
                CP_ASYNC(daddr, (const char*)(s + (long)row * Kd) + cb);
            }
        }
        CP_COMMIT();
    };

    float acc[2][8][4];
    #pragma unroll
    for (int a = 0; a < 2; a++)
        #pragma unroll
        for (int b = 0; b < 8; b++)
            #pragma unroll
            for (int c = 0; c < 4; c++) acc[a][b][c] = 0.f;

    const int nb = kbe - kb0;
    load_blk(kb0, 0);
    if (nb > 1) load_blk(kb0 + 1, 1);

    for (int t = 0; t < nb; t++) {
        int st = t % NSTAGE;
        if (t + 1 < nb) CP_WAIT(1); else CP_WAIT(0);
        __syncthreads();
        if (t + 2 < nb) load_blk(kb0 + t + 2, (t + 2) % NSTAGE);

        char* base = smem + st * STAGE_B;
        uint32_t baseAh = smem_u32(base);
        uint32_t baseAl = baseAh + TILE_B;
        uint32_t baseBh = baseAh + 2 * TILE_B;
        uint32_t baseBl = baseAh + 3 * TILE_B;

        #pragma unroll
        for (int ks = 0; ks < 4; ks++) {
            uint32_t ah[2][4], al[2][4];
            int arow = wm * 32 + (lane & 15);
            int acb  = ks * 32 + (lane >> 4) * 16;
            #pragma unroll
            for (int tm = 0; tm < 2; tm++) {
                uint32_t off = (arow + tm * 16) * (LDT * 2) + acb;
                ldsm_x4(ah[tm], baseAh + off);
                if (nProd == 3) ldsm_x4(al[tm], baseAl + off);
            }
            uint32_t bh[8][2], bl[8][2];
            int q = lane >> 3;
            int brow_base = wn * 64 + ((q & 2) ? 8 : 0) + (lane & 7);
            int bcb = ks * 32 + (q & 1) * 16;
            #pragma unroll
            for (int p = 0; p < 4; p++) {
                uint32_t off = (brow_base + p * 16) * (LDT * 2) + bcb;
                uint32_t r[4];
                ldsm_x4(r, baseBh + off);
                bh[2*p][0] = r[0]; bh[2*p][1] = r[1]; bh[2*p+1][0] = r[2]; bh[2*p+1][1] = r[3];
                ldsm_x4(r, baseBl + off);
                bl[2*p][0] = r[0]; bl[2*p][1] = r[1]; bl[2*p+1][0] = r[2]; bl[2*p+1][1] = r[3];
            }
            #pragma unroll
            for (int tm = 0; tm < 2; tm++)
                #pragma unroll
                for (int tn = 0; tn < 8; tn++) {
                    mma16816(acc[tm][tn], ah[tm], bh[tn]);
                    mma16816(acc[tm][tn], ah[tm], bl[tn]);
                    if (nProd == 3) mma16816(acc[tm][tn], al[tm], bh[tn]);
                }
        }
    }
    __syncthreads();

    #pragma unroll
    for (int tm = 0; tm < 2; tm++) {
        #pragma unroll
        for (int half = 0; half < 2; half++) {
            int m = m0 + wm * 32 + tm * 16 + (lane >> 2) + half * 8;
            #pragma unroll
            for (int tn = 0; tn < 8; tn++) {
                int n = n0 + wn * 64 + tn * 8 + (lane & 3) * 2;
                float v0 = alpha * acc[tm][tn][half * 2 + 0];
                float v1 = alpha * acc[tm][tn][half * 2 + 1];
                if (bias) { v0 += bias[n]; v1 += bias[n + 1]; }
                if (doRelu) { v0 = fmaxf(v0, 0.f); v1 = fmaxf(v1, 0.f); }
                long idx = (long)m * N + n;
                if (Cf) {
                    if (accFlag) { Cf[idx] += v0; Cf[idx + 1] += v1; }
                    else { Cf[idx] = v0; Cf[idx + 1] = v1; }
                } else {
                    __nv_bfloat16 h0 = __float2bfloat16(v0);
                    __nv_bfloat16 h1 = __float2bfloat16(v1);
                    __nv_bfloat162 hp; hp.x = h0; hp.y = h1;
                    *reinterpret_cast<__nv_bfloat162*>(&Chi[idx]) = hp;
                    __nv_bfloat162 lp;
                    lp.x = __float2bfloat16(v0 - __bfloat162float(h0));
                    lp.y = __float2bfloat16(v1 - __bfloat162float(h1));
                    *reinterpret_cast<__nv_bfloat162*>(&Clo[idx]) = lp;
                }
            }
        }
    }

    // fused per-CTA row-max / sum-exp partials (LSE)
    if (pmax) {
        float* sm8 = (float*)smem;                    // [128][8]
        float* rowred = (float*)(smem + 128 * 8 * 4); // [128]
        int slot = wn * 4 + (lane & 3);
        __syncthreads();
        #pragma unroll
        for (int tm = 0; tm < 2; tm++)
            #pragma unroll
            for (int half = 0; half < 2; half++) {
                int rl = wm * 32 + tm * 16 + (lane >> 2) + half * 8;
                float lm = -1e30f;
                #pragma unroll
                for (int tn = 0; tn < 8; tn++)
                    #pragma unroll
                    for (int e = 0; e < 2; e++)
                        lm = fmaxf(lm, alpha * acc[tm][tn][half * 2 + e]);
                sm8[rl * 8 + slot] = lm;
            }
        __syncthreads();
        if (tid < 128) {
            float mR = -1e30f;
            #pragma unroll
            for (int i = 0; i < 8; i++) mR = fmaxf(mR, sm8[tid * 8 + i]);
            rowred[tid] = mR;
        }
        __syncthreads();
        #pragma unroll
        for (int tm = 0; tm < 2; tm++)
            #pragma unroll
            for (int half = 0; half < 2; half++) {
                int rl = wm * 32 + tm * 16 + (lane >> 2) + half * 8;
                float rm = rowred[rl];
                float ls = 0.f;
                #pragma unroll
                for (int tn = 0; tn < 8; tn++)
                    #pragma unroll
                    for (int e = 0; e < 2; e++)
                        ls += expf(alpha * acc[tm][tn][half * 2 + e] - rm);
                sm8[rl * 8 + slot] = ls;
            }
        __syncthreads();
        if (tid < 128) {
            float sR = 0.f;
            #pragma unroll
            for (int i = 0; i < 8; i++) sR += sm8[tid * 8 + i];
            long r = m0 + tid;
            pmax[r * nxb + blockIdx.x] = rowred[tid];
            psum[r * nxb + blockIdx.x] = sR;
        }
    }
}

// ---------------- SIMT 64x64 tile core (small fp32 GEMMs) ------------------
__device__ __forceinline__ void gemm64_acc(
    const float* __restrict__ A, const float* __restrict__ Bm, bool transB,
    int N, int Kd, int m0, int n0, int rollL, int rollOff,
    float As[32][64], float Bs[32][64], float acc[4][4])
{
    int tid = threadIdx.x;
    int tx = tid & 15, ty = tid >> 4;
    int arow = tid >> 2, ak0 = (tid & 3) * 8;
    int gm = m0 + arow;
    if (rollL) {
        int g = gm / rollL, l = gm - g * rollL;
        l += rollOff; if (l >= rollL) l -= rollL;
        gm = g * rollL + l;
    }
    const float* Aptr = A + (long)gm * Kd + ak0;
    for (int k0 = 0; k0 < Kd; k0 += 32) {
        #pragma unroll
        for (int i = 0; i < 8; i += 4) {
            float4 v = *(const float4*)(Aptr + k0 + i);
            As[ak0+i+0][arow] = v.x; As[ak0+i+1][arow] = v.y;
            As[ak0+i+2][arow] = v.z; As[ak0+i+3][arow] = v.w;
        }
        if (transB) {
            int br = tid >> 2, bk0 = (tid & 3) * 8;
            const float* Bp = Bm + (long)(n0 + br) * Kd + k0 + bk0;
            #pragma unroll
            for (int i = 0; i < 8; i += 4) {
                float4 v = *(const float4*)(Bp + i);
                Bs[bk0+i+0][br] = v.x; Bs[bk0+i+1][br] = v.y;
                Bs[bk0+i+2][br] = v.z; Bs[bk0+i+3][br] = v.w;
            }
        } else {
            int bk = tid >> 3, bn0 = (tid & 7) * 8;
            const float* Bp = Bm + (long)(k0 + bk) * N + n0 + bn0;
            #pragma unroll
            for (int i = 0; i < 8; i += 4)
                *(float4*)&Bs[bk][bn0 + i] = *(const float4*)(Bp + i);
        }
        __syncthreads();
        #pragma unroll
        for (int k = 0; k < 32; k++) {
            float a[4], b[4];
            *(float4*)a = *(const float4*)&As[k][ty * 4];
            *(float4*)b = *(const float4*)&Bs[k][tx * 4];
            #pragma unroll
            for (int i = 0; i < 4; i++)
                #pragma unroll
                for (int j = 0; j < 4; j++)
                    acc[i][j] += a[i] * b[j];
        }
        __syncthreads();
    }
}

// pair_k: z=0: tmp1 = relu(roll(xsa,+1) @ wt); z=1: tmp2 = relu(roll(xsa,-1) @ wtc^T)
__global__ __launch_bounds__(256) void pair_k(
    const float* __restrict__ xsa, const float* __restrict__ wt,
    const float* __restrict__ wtc, float* __restrict__ tmp1, float* __restrict__ tmp2)
{
    __shared__ float As[32][64];
    __shared__ float Bs[32][64];
    int m0 = blockIdx.y * 64, n0 = blockIdx.x * 64;
    float acc[4][4] = {};
    float* C;
    if (blockIdx.z == 0) {
        gemm64_acc(xsa, wt, false, EE, EE, m0, n0, LL, LL - 1, As, Bs, acc);
        C = tmp1;
    } else {
        gemm64_acc(xsa, wtc, true, EE, EE, m0, n0, LL, 1, As, Bs, acc);
        C = tmp2;
    }
    int tid = threadIdx.x, tx = tid & 15, ty = tid >> 4;
    #pragma unroll
    for (int i = 0; i < 4; i++) {
        int m = m0 + ty * 4 + i;
        #pragma unroll
        for (int j = 0; j < 4; j++) {
            int n = n0 + tx * 4 + j;
            C[(long)m * EE + n] = fmaxf(acc[i][j], 0.f);
        }
    }
}

// sum3_k: xsad = tmp1 @ wtc + tmp2 @ wt^T + z @ wu^T + bt
__global__ __launch_bounds__(256) void sum3_k(
    const float* __restrict__ tmp1, const float* __restrict__ tmp2,
    const float* __restrict__ z, const float* __restrict__ wt,
    const float* __restrict__ wtc, const float* __restrict__ wu,
    const float* __restrict__ bt, float* __restrict__ xsad)
{
    __shared__ float As[32][64];
    __shared__ float Bs[32][64];
    int m0 = blockIdx.y * 64, n0 = blockIdx.x * 64;
    float acc[4][4] = {};
    gemm64_acc(tmp1, wtc, false, EE, EE, m0, n0, 0, 0, As, Bs, acc);
    gemm64_acc(tmp2, wt,  true,  EE, EE, m0, n0, 0, 0, As, Bs, acc);
    gemm64_acc(z,    wu,  true,  EE, EE, m0, n0, 0, 0, As, Bs, acc);
    int tid = threadIdx.x, tx = tid & 15, ty = tid >> 4;
    #pragma unroll
    for (int i = 0; i < 4; i++) {
        int m = m0 + ty * 4 + i;
        #pragma unroll
        for (int j = 0; j < 4; j++) {
            int n = n0 + tx * 4 + j;
            xsad[(long)m * EE + n] = acc[i][j] + bt[n];
        }
    }
}

// ---------------- split / transpose-split ----------------------------------
__global__ void split_k(const float* __restrict__ s, __nv_bfloat16* __restrict__ h,
                        __nv_bfloat16* __restrict__ l, long n)
{
    long i = blockIdx.x * 256L + threadIdx.x;
    if (i < n) {
        float v = s[i];
        __nv_bfloat16 a = __float2bfloat16(v);
        h[i] = a;
        l[i] = __float2bfloat16(v - __bfloat162float(a));
    }
}
__global__ void tsplit_k(const float* __restrict__ s, __nv_bfloat16* __restrict__ h,
                         __nv_bfloat16* __restrict__ l, int R, int C, long sS, long sD)
{
    __shared__ float t[32][33];
    int b = blockIdx.z;
    s += (long)b * sS; h += (long)b * sD; l += (long)b * sD;
    int r0 = blockIdx.y * 32, c0 = blockIdx.x * 32;
    int x = threadIdx.x, y = threadIdx.y;
    #pragma unroll
    for (int i = 0; i < 32; i += 8) t[y + i][x] = s[(long)(r0 + y + i) * C + c0 + x];
    __syncthreads();
    #pragma unroll
    for (int i = 0; i < 32; i += 8) {
        float v = t[x][y + i];
        __nv_bfloat16 a = __float2bfloat16(v);
        long idx = (long)(c0 + y + i) * R + r0 + x;
        h[idx] = a;
        l[idx] = __float2bfloat16(v - __bfloat162float(a));
    }
}

// ---------------- elementwise / reduction kernels --------------------------
__device__ __forceinline__ float blkSum256(float v) {
    __shared__ float sh[8];
    int lane = threadIdx.x & 31, w = threadIdx.x >> 5;
    #pragma unroll
    for (int o = 16; o; o >>= 1) v += __shfl_xor_sync(0xffffffffu, v, o);
    __syncthreads();
    if (lane == 0) sh[w] = v;
    __syncthreads();
    float r = sh[0];
    #pragma unroll
    for (int i = 1; i < 8; i++) r += sh[i];
    return r;
}
__device__ __forceinline__ float blkMax256(float v) {
    __shared__ float sh[8];
    int lane = threadIdx.x & 31, w = threadIdx.x >> 5;
    #pragma unroll
    for (int o = 16; o; o >>= 1) v = fmaxf(v, __shfl_xor_sync(0xffffffffu, v, o));
    __syncthreads();
    if (lane == 0) sh[w] = v;
    __syncthreads();
    float r = sh[0];
    #pragma unroll
    for (int i = 1; i < 8; i++) r = fmaxf(r, sh[i]);
    return r;
}
__device__ __forceinline__ void emit_planes(__nv_bfloat16* h, __nv_bfloat16* l,
                                            long idx, float v) {
    __nv_bfloat16 a = __float2bfloat16(v);
    h[idx] = a;
    l[idx] = __float2bfloat16(v - __bfloat162float(a));
}

__global__ void embed_norm_k(const int* __restrict__ masked, const float* __restrict__ embed,
                             float* __restrict__ z, float* __restrict__ xsa,
                             __nv_bfloat16* __restrict__ xh, __nv_bfloat16* __restrict__ xl)
{
    long row = blockIdx.x; int t = threadIdx.x;
    float v = embed[(long)masked[row] * EE + t];
    float mean = blkSum256(v) * (1.f / EE);
    float d = v - mean;
    float var = fmaxf(blkSum256(d * d) * (1.f / (EE - 1)), 0.f);
    float o = v / (1.f + sqrtf(var));
    long i = row * EE + t;
    z[i] = o;
    xsa[i] = o;
    emit_planes(xh, xl, i, o);
}

__global__ void softmax512_k(const float* __restrict__ h,
                             __nv_bfloat16* __restrict__ ph)
{
    long row = blockIdx.x;
    const float* p = h + row * 512;
    int t = threadIdx.x;
    float a = p[t], b = p[t + 256];
    float m = blkMax256(fmaxf(a, b));
    float ea = __expf(a - m), eb = __expf(b - m);
    float s = blkSum256(ea + eb);
    float inv = 1.f / s;
    ph[row * 512 + t] = __float2bfloat16(ea * inv);
    ph[row * 512 + t + 256] = __float2bfloat16(eb * inv);
}

__global__ void update_k(const float* __restrict__ xsad, const float* __restrict__ xid,
                         float* __restrict__ xsa,
                         __nv_bfloat16* __restrict__ xh, __nv_bfloat16* __restrict__ xl)
{
    long row = blockIdx.x; int t = threadIdx.x;
    long i = row * EE + t;
    const long S = (long)BL * EE;
    float s = xsad[i] + ((xid[i] + xid[i + S]) + (xid[i + 2 * S] + xid[i + 3 * S]));
    float mean = blkSum256(s) * (1.f / EE);
    float d = s - mean;
    float var = fmaxf(blkSum256(d * d) * (1.f / (EE - 1)), 0.f);
    float a = s / (1.f + sqrtf(var));
    float x = xsa[i] + 0.05f * a;
    float mean2 = blkSum256(x) * (1.f / EE);
    float d2 = x - mean2;
    float var2 = fmaxf(blkSum256(d2 * d2) * (1.f / (EE - 1)), 0.f);
    float o = x / (1.f + sqrtf(var2));
    xsa[i] = o;
    emit_planes(xh, xl, i, o);
}

__global__ void gather_lptok_k(const float* __restrict__ xsa, const int* __restrict__ mask,
                               __nv_bfloat16* __restrict__ h, __nv_bfloat16* __restrict__ l)
{
    int r = blockIdx.x;
    int b = r / LMM, lm = r % LMM;
    int pos = mask[b * LMM + lm];
    int t = threadIdx.x;
    float v = xsa[((long)b * LL + pos) * EE + t];
    emit_planes(h, l, (long)r * EE + t, v);
}

__global__ void lse_reduce_k(const float* __restrict__ pmax, const float* __restrict__ psum,
                             float* __restrict__ lse)
{
    long row = blockIdx.x;
    int t = threadIdx.x;
    const float* pm = pmax + row * NXB;
    const float* ps = psum + row * NXB;
    float m = -1e30f;
    for (int i = t; i < NXB; i += 256) m = fmaxf(m, pm[i]);
    m = blkMax256(m);
    float s = 0.f;
    for (int i = t; i < NXB; i += 256) s += ps[i] * expf(pm[i] - m);
    s = blkSum256(s);
    if (!t) lse[row] = m + logf(s);
}

__global__ void final_k(const float* __restrict__ logits, const float* __restrict__ lse,
                        const int* __restrict__ unmasked, const int* __restrict__ mask,
                        float* __restrict__ out)
{
    int b = blockIdx.x, lm = threadIdx.x;
    int pos = mask[b * LMM + lm];
    int tgt = unmasked[b * LL + pos];
    float v[KNN]; float m = -1e30f;
    #pragma unroll
    for (int kn = 0; kn < KNN; kn++) {
        int n = b * (LMM * KNN) + lm * KNN + kn;
        v[kn] = logits[(long)n * GG + tgt] - lse[n];
        m = fmaxf(m, v[kn]);
    }
    float s = 0.f;
    #pragma unroll
    for (int kn = 0; kn < KNN; kn++) s += expf(v[kn] - m);
    float cent = m + logf(s) - logf((float)KNN);
    __shared__ float sh[LMM];
    sh[lm] = cent; __syncthreads();
    for (int o = 32; o; o >>= 1) { if (lm < o) sh[lm] += sh[lm + o]; __syncthreads(); }
    if (!lm) out[b] = -sh[0] / (float)LMM;
}

// ---------------- host orchestration ---------------------------------------
typedef __nv_bfloat16 bf;
template <typename T> static inline T* sym(const void* s) {
    void* p = nullptr; cudaGetSymbolAddress(&p, s); return (T*)p;
}
static inline void tc(cudaStream_t st, const bf* Ah, const bf* Al, const bf* Bh, const bf* Bl,
                      const float* bias, float* Cf, bf* Ch, bf* Cl,
                      int M, int N, int K, long sA, long sB, long sC, int batch,
                      float alpha, int relu, int accF = 0, int splitK = 1,
                      float* pmax = nullptr, float* psum = nullptr, int nProd = 3)
{
    int kcT = 1;
    int zdim = batch;
    if (splitK > 1) {
        int nbAll = K >> 6;
        kcT = (nbAll + splitK - 1) / splitK;
        zdim = splitK;
    }
    dim3 g(N / 128, M / 128, zdim);
    tc_gemm<<<g, 256, TCSM, st>>>(Ah, Al, Bh, Bl, bias, Cf, Ch, Cl, pmax, psum, N / 128,
                                  M, N, K, sA, sB, sC, alpha, relu, accF, splitK, kcT, nProd);
}

extern "C" void kernel_launch(void* const* d_in, const int* in_sizes, int n_in,
                              void* d_out, int out_size)
{
    const int*   masked   = (const int*)  d_in[0];
    const int*   unmasked = (const int*)  d_in[1];
    const int*   mask     = (const int*)  d_in[2];
    const float* embed    = (const float*)d_in[3];
    const float* Wt       = (const float*)d_in[4];
    const float* bt       = (const float*)d_in[5];
    const float* Wtc      = (const float*)d_in[6];
    const float* Wq       = (const float*)d_in[7];
    const float* Wd       = (const float*)d_in[8];
    const float* Wo       = (const float*)d_in[9];
    const float* Wu       = (const float*)d_in[10];
    const float* Wem      = (const float*)d_in[11];
    const float* Wkc      = (const float*)d_in[12];
    const float* bkc      = (const float*)d_in[13];
    float* out = (float*)d_out;

    static bool inited = false;
    static cudaStream_t s2 = nullptr;
    static cudaEvent_t evFork = nullptr, evS = nullptr;
    if (!inited) {
        cudaFuncSetAttribute(tc_gemm, cudaFuncAttributeMaxDynamicSharedMemorySize, TCSM);
        cudaStreamCreateWithFlags(&s2, cudaStreamNonBlocking);
        cudaEventCreateWithFlags(&evFork, cudaEventDisableTiming);
        cudaEventCreateWithFlags(&evS, cudaEventDisableTiming);
        inited = true;
    }
    cudaStream_t s0 = 0;

    float *z = sym<float>(g_z), *xsa = sym<float>(g_xsa), *xsad = sym<float>(g_xsad);
    float *tmp1 = sym<float>(g_tmp1), *tmp2 = sym<float>(g_tmp2), *xid = sym<float>(g_xid);
    float *h = sym<float>(g_h), *logits = sym<float>(g_logits), *lse = sym<float>(g_lse);
    float *pmax = sym<float>(g_pmax), *psum = sym<float>(g_psum);
    bf *xsaP = sym<bf>(g_xsaP), *xsaTP = sym<bf>(g_xsaTP);
    bf *qP = sym<bf>(g_qP), *pP = sym<bf>(g_pP), *yP = sym<bf>(g_yP), *ydP = sym<bf>(g_ydP);
    bf *wqP = sym<bf>(g_wqP), *wdP = sym<bf>(g_wdP), *woTP = sym<bf>(g_woTP);
    bf *embP = sym<bf>(g_embP), *kcP = sym<bf>(g_kcP), *wemTP = sym<bf>(g_wemTP);
    bf *lptP = sym<bf>(g_lptP), *xx1P = sym<bf>(g_xx1P), *tbP = sym<bf>(g_tbP);
    bf *xx2P = sym<bf>(g_xx2P), *vP = sym<bf>(g_vP);

    embed_norm_k<<<BL, 256, 0, s0>>>(masked, embed, z, xsa, xsaP, xsaP + PXSA);
    split_k<<<(PWQA + 255) / 256, 256, 0, s0>>>(Wq, wqP, wqP + PWQA, PWQA);

    for (int d = 0; d < DL; d++) {
        const float* wt  = Wt  + (long)d * EE * EE;
        const float* btd = bt  + (long)d * EE;
        const float* wtc = Wtc + (long)d * EE * EE;
        const float* wu  = Wu  + (long)d * EE * EE;
        const bf* wqh = wqP + (long)d * KE * EE;  const bf* wql = wqh + PWQA;
        const bf* wdh = wdP + (long)d * KE * KE;  const bf* wdl = wdh + PWDA;
        const bf* woh = woTP + (long)d * EE * KE; const bf* wol = woh + PWOA;

        cudaEventRecord(evFork, s0);
        cudaStreamWaitEvent(s2, evFork, 0);
        if (d == 0) {
            split_k<<<(PWDA + 255) / 256, 256, 0, s2>>>(Wd, wdP, wdP + PWDA, PWDA);
            split_k<<<(PEMB + 255) / 256, 256, 0, s2>>>(embed, embP, embP + PEMB, PEMB);
            split_k<<<(PKC + 255) / 256, 256, 0, s2>>>(Wkc, kcP, kcP + PKC, PKC);
            { dim3 b(32, 8), g(EE / 32, KE / 32, DL);
              tsplit_k<<<g, b, 0, s2>>>(Wo, woTP, woTP + PWOA, KE, EE, (long)KE * EE, (long)EE * KE); }
            { dim3 b(32, 8), g(EE / 32, EE / 32, 1);
              tsplit_k<<<g, b, 0, s2>>>(Wem, wemTP, wemTP + PWEM, EE, EE, 0, 0); }
        }
        { dim3 b(32, 8), g(EE / 32, LL / 32, BB);
          tsplit_k<<<g, b, 0, s2>>>(xsa, xsaTP, xsaTP + PXSAT, LL, EE, (long)LL * EE, (long)EE * LL); }
        { dim3 g(EE / 64, BL / 64, 2);
          pair_k<<<g, 256, 0, s2>>>(xsa, wt, wtc, tmp1, tmp2); }
        { dim3 g(EE / 64, BL / 64, 1);
          sum3_k<<<g, 256, 0, s2>>>(tmp1, tmp2, z, wt, wtc, wu, btd, xsad); }
        cudaEventRecord(evS, s2);

        tc(s0, xsaP, xsaP + PXSA, wqh, wql, nullptr, nullptr, qP, qP + PQ,
           BL, KE, EE, 0, 0, 0, 1, 1.f, 0);
        tc(s0, qP, qP + PQ, xsaP, xsaP + PXSA, nullptr, h, nullptr, nullptr,
           LK, LL, EE, (long)LK * EE, (long)LL * EE, (long)LK * LL, BB, 1.f / 16.f, 0);
        softmax512_k<<<BB * LK, 256, 0, s0>>>(h, pP);

        cudaStreamWaitEvent(s0, evS, 0);

        // y = P @ xsa — 2-product mode (P hi plane only)
        tc(s0, pP, pP, xsaTP, xsaTP + PXSAT, nullptr, nullptr, yP, yP + PY,
           LK, EE, LL, (long)LK * LL, (long)EE * LL, (long)LK * EE, BB, 1.f, 0,
           0, 1, nullptr, nullptr, /*nProd=*/2);
        tc(s0, yP, yP + PY, wdh, wdl, nullptr, nullptr, ydP, ydP + PYD,
           BL, KE, KE, 0, 0, 0, 1, 1.f, 1);
        // xid = yd @ wo — deterministic split-K=4 into 4 slabs (stride BL*EE)
        tc(s0, ydP, ydP + PYD, woh, wol, nullptr, xid, nullptr, nullptr,
           BL, EE, KE, 0, 0, (long)BL * EE, 1, 1.f, 0, 0, /*splitK=*/4);
        update_k<<<BL, 256, 0, s0>>>(xsad, xid, xsa, xsaP, xsaP + PXSA);
    }

    // ---- head ----
    cudaEventRecord(evFork, s0);
    cudaStreamWaitEvent(s2, evFork, 0);
    { dim3 b(32, 8), g(EE / 32, LL / 32, BB);
      tsplit_k<<<g, b, 0, s2>>>(xsa, xsaTP, xsaTP + PXSAT, LL, EE, (long)LL * EE, (long)EE * LL); }
    cudaEventRecord(evS, s2);

    gather_lptok_k<<<BB * LMM, 256, 0, s0>>>(xsa, mask, lptP, lptP + PLPT);
    tc(s0, lptP, lptP + PLPT, kcP, kcP + PKC, bkc, nullptr, xx1P, xx1P + PXX1,
       BB * LMM, KNN * EE, EE, 0, 0, 0, 1, 1.f, 0);
    tc(s0, xx1P, xx1P + PXX1, xsaP, xsaP + PXSA, nullptr, nullptr, tbP, tbP + PTB,
       LMM * KNN, LL, EE, (long)LMM * KNN * EE, (long)LL * EE, (long)LMM * KNN * LL, BB, 1.f, 0);
    cudaStreamWaitEvent(s0, evS, 0);
    tc(s0, tbP, tbP + PTB, xsaTP, xsaTP + PXSAT, nullptr, nullptr, xx2P, xx2P + PXX2,
       LMM * KNN, EE, LL, (long)LMM * KNN * LL, (long)EE * LL, (long)LMM * KNN * EE, BB, 1.f, 0);
    tc(s0, xx2P, xx2P + PXX2, wemTP, wemTP + PWEM, nullptr, nullptr, vP, vP + PV,
       BB * LMM * KNN, EE, EE, 0, 0, 0, 1, 1.f, 0);
    tc(s0, vP, vP + PV, embP, embP + PEMB, nullptr, logits, nullptr, nullptr,
       NR, GG, EE, 0, 0, 0, 1, 1.f, 0, 0, 1, pmax, psum);
    lse_reduce_k<<<NR, 256, 0, s0>>>(pmax, psum, lse);
    final_k<<<BB, LMM, 0, s0>>>(logits, lse, unmasked, mask, out);
}

// round 17
// speedup vs baseline: 1.0457x; 1.0169x over previous
#include <cuda_runtime.h>
#include <cuda_bf16.h>
#include <math.h>
#include <stdint.h>

#define BB   4
#define LL   512
#define EE   256
#define KH   8
#define DL   6
#define KNN  4
#define GG   32000
#define LMM  64
#define BL   (BB*LL)          // 2048
#define KE   (KH*EE)          // 2048
#define LK   (LL*KH)          // 4096
#define NXB  (GG/128)         // 250 logits col-blocks
#define NR   (BB*LMM*KNN)     // 1024 head rows

// plane sizes (elements per plane)
#define PXSA  ((long)BL*EE)
#define PXSAT ((long)BB*EE*LL)
#define PQ    ((long)BL*KE)
#define PP    ((long)BB*LK*LL)
#define PY    ((long)BL*KE)
#define PYD   ((long)BL*KE)
#define PWQA  ((long)DL*KE*EE)
#define PWDA  ((long)DL*KE*KE)
#define PWOA  ((long)DL*EE*KE)
#define PEMB  ((long)GG*EE)
#define PKC   ((long)KNN*EE*EE)
#define PWEM  ((long)EE*EE)
#define PLPT  ((long)BB*LMM*EE)
#define PXX1  ((long)BB*LMM*KNN*EE)
#define PTB   ((long)BB*LMM*KNN*LL)
#define PXX2  ((long)BB*LMM*KNN*EE)
#define PV    ((long)BB*LMM*KNN*EE)

// ---------------- static scratch -------------------------------------------
__device__ float g_z    [BL*EE];
__device__ float g_xsa  [BL*EE];
__device__ float g_xsad [BL*EE];
__device__ float g_tmp1 [BL*EE];
__device__ float g_tmp2 [BL*EE];
__device__ float g_xid  [4*BL*EE];                 // 4 split-K slabs
__device__ float g_h    [(long)BB*LK*LL];          // 32 MB fp32
__device__ float g_logits[(long)NR*GG];            // 131 MB
__device__ float g_lse  [NR];
__device__ float g_pmax [(long)NR*NXB];
__device__ float g_psum [(long)NR*NXB];

__device__ __nv_bfloat16 g_xsaP [2*PXSA];
__device__ __nv_bfloat16 g_xsaTP[2*PXSAT];
__device__ __nv_bfloat16 g_qP   [2*PQ];
__device__ __nv_bfloat16 g_pP   [PP];              // hi plane only
__device__ __nv_bfloat16 g_yP   [2*PY];
__device__ __nv_bfloat16 g_ydP  [2*PYD];
__device__ __nv_bfloat16 g_wqP  [2*PWQA];
__device__ __nv_bfloat16 g_wdP  [2*PWDA];
__device__ __nv_bfloat16 g_woTP [2*PWOA];
__device__ __nv_bfloat16 g_embP [2*PEMB];
__device__ __nv_bfloat16 g_kcP  [2*PKC];
__device__ __nv_bfloat16 g_wemTP[2*PWEM];
__device__ __nv_bfloat16 g_lptP [2*PLPT];
__device__ __nv_bfloat16 g_xx1P [2*PXX1];
__device__ __nv_bfloat16 g_tbP  [2*PTB];
__device__ __nv_bfloat16 g_xx2P [2*PXX2];
__device__ __nv_bfloat16 g_vP   [2*PV];

// ---------------- mma.sync helpers -----------------------------------------
__device__ __forceinline__ uint32_t smem_u32(const void* p) {
    uint32_t a;
    asm("{ .reg .u64 t; cvta.to.shared.u64 t, %1; cvt.u32.u64 %0, t; }" : "=r"(a) : "l"(p));
    return a;
}
__device__ __forceinline__ void ldsm_x4(uint32_t* r, uint32_t addr) {
    asm volatile("ldmatrix.sync.aligned.m8n8.x4.shared.b16 {%0,%1,%2,%3}, [%4];"
        : "=r"(r[0]), "=r"(r[1]), "=r"(r[2]), "=r"(r[3]) : "r"(addr));
}
__device__ __forceinline__ void mma16816(float* c, const uint32_t* a, const uint32_t* b) {
    asm volatile("mma.sync.aligned.m16n8k16.row.col.f32.bf16.bf16.f32 "
        "{%0,%1,%2,%3}, {%4,%5,%6,%7}, {%8,%9}, {%0,%1,%2,%3};"
        : "+f"(c[0]), "+f"(c[1]), "+f"(c[2]), "+f"(c[3])
        : "r"(a[0]), "r"(a[1]), "r"(a[2]), "r"(a[3]), "r"(b[0]), "r"(b[1]));
}
#define CP_ASYNC(dst, src) \
    asm volatile("cp.async.ca.shared.global [%0], [%1], 16;" :: "r"(dst), "l"(src))
#define CP_COMMIT()  asm volatile("cp.async.commit_group;" ::: "memory")
#define CP_WAIT(n)   asm volatile("cp.async.wait_group %0;" :: "n"(n) : "memory")

// ---------------- tc_gemm ---------------------------------------------------
// 128x128 CTA tile, 256 threads, 4x2 warp grid, warp tile 32x64.
// K-tile = 64, 3-stage cp.async pipeline.
// nProd==3: acc = Ah*Bh + Ah*Bl + Al*Bh  (fp32-emulating)
// nProd==2: acc = Ah*Bh + Ah*Bl          (A lo-plane ignored, not loaded)
// splitK>1: blockIdx.z = chunk, writes slab Cf + chunk*sC (deterministic).
// pmax/psum non-null: fused per-CTA row max / sum-exp partials (for LSE).
#define LDT 72
#define TILE_B (128*LDT*2)
#define STAGE_B (4*TILE_B)
#define NSTAGE 3
#define TCSM (NSTAGE*STAGE_B)         // 221184
__global__ __launch_bounds__(256, 1) void tc_gemm(
    const __nv_bfloat16* __restrict__ Ah, const __nv_bfloat16* __restrict__ Al,
    const __nv_bfloat16* __restrict__ Bh, const __nv_bfloat16* __restrict__ Bl,
    const float* __restrict__ bias, float* __restrict__ Cf,
    __nv_bfloat16* __restrict__ Chi, __nv_bfloat16* __restrict__ Clo,
    float* __restrict__ pmax, float* __restrict__ psum, int nxb,
    int M, int N, int Kd, long sA, long sB, long sC, float alpha, int doRelu,
    int accFlag, int splitK, int kcTiles, int nProd)
{
    extern __shared__ char smem[];
    int tid = threadIdx.x, lane = tid & 31, wid = tid >> 5;
    int wm = wid >> 1, wn = wid & 1;
    const int nbAll = Kd >> 6;
    long bz = blockIdx.z;
    int kb0 = 0, kbe = nbAll;
    if (splitK > 1) {
        int c = (int)bz; bz = 0;
        kb0 = c * kcTiles;
        kbe = min(nbAll, kb0 + kcTiles);
        if (Cf) Cf += (long)c * sC;        // slab per chunk
    } else {
        if (Cf) Cf += bz * sC;
    }
    Ah += bz * sA; Al += bz * sA; Bh += bz * sB; Bl += bz * sB;
    if (Chi) { Chi += bz * sC; Clo += bz * sC; }
    int m0 = blockIdx.y * 128, n0 = blockIdx.x * 128;

    const __nv_bfloat16* srcs[4] = { Ah + (long)m0 * Kd, Al + (long)m0 * Kd,
                                     Bh + (long)n0 * Kd, Bl + (long)n0 * Kd };

    auto load_blk = [&](int kb, int st) {
        char* base = smem + st * STAGE_B;
        #pragma unroll
        for (int tI = 0; tI < 4; tI++) {
            if (tI == 1 && nProd == 2) continue;     // skip A lo plane
            const __nv_bfloat16* s = srcs[tI] + (long)kb * 64;
            char* d = base + tI * TILE_B;
            #pragma unroll
            for (int i = 0; i < 4; i++) {
                int idx = tid + i * 256;
                int row = idx >> 3, cb = (idx & 7) * 16;
                uint32_t daddr = smem_u32(d + row * (LDT * 2) + cb);
                CP_ASYNC(daddr, (const char*)(s + (long)row * Kd) + cb);
            }
        }
        CP_COMMIT();
    };

    float acc[2][8][4];
    #pragma unroll
    for (int a = 0; a < 2; a++)
        #pragma unroll
        for (int b = 0; b < 8; b++)
            #pragma unroll
            for (int c = 0; c < 4; c++) acc[a][b][c] = 0.f;

    const int nb = kbe - kb0;
    load_blk(kb0, 0);
    if (nb > 1) load_blk(kb0 + 1, 1);

    for (int t = 0; t < nb; t++) {
        int st = t % NSTAGE;
        if (t + 1 < nb) CP_WAIT(1); else CP_WAIT(0);
        __syncthreads();
        if (t + 2 < nb) load_blk(kb0 + t + 2, (t + 2) % NSTAGE);

        char* base = smem + st * STAGE_B;
        uint32_t baseAh = smem_u32(base);
        uint32_t baseAl = baseAh + TILE_B;
        uint32_t baseBh = baseAh + 2 * TILE_B;
        uint32_t baseBl = baseAh + 3 * TILE_B;

        #pragma unroll
        for (int ks = 0; ks < 4; ks++) {
            uint32_t ah[2][4], al[2][4];
            int arow = wm * 32 + (lane & 15);
            int acb  = ks * 32 + (lane >> 4) * 16;
            #pragma unroll
            for (int tm = 0; tm < 2; tm++) {
                uint32_t off = (arow + tm * 16) * (LDT * 2) + acb;
                ldsm_x4(ah[tm], baseAh + off);
                if (nProd == 3) ldsm_x4(al[tm], baseAl + off);
            }
            uint32_t bh[8][2], bl[8][2];
            int q = lane >> 3;
            int brow_base = wn * 64 + ((q & 2) ? 8 : 0) + (lane & 7);
            int bcb = ks * 32 + (q & 1) * 16;
            #pragma unroll
            for (int p = 0; p < 4; p++) {
                uint32_t off = (brow_base + p * 16) * (LDT * 2) + bcb;
                uint32_t r[4];
                ldsm_x4(r, baseBh + off);
                bh[2*p][0] = r[0]; bh[2*p][1] = r[1]; bh[2*p+1][0] = r[2]; bh[2*p+1][1] = r[3];
                ldsm_x4(r, baseBl + off);
                bl[2*p][0] = r[0]; bl[2*p][1] = r[1]; bl[2*p+1][0] = r[2]; bl[2*p+1][1] = r[3];
            }
            #pragma unroll
            for (int tm = 0; tm < 2; tm++)
                #pragma unroll
                for (int tn = 0; tn < 8; tn++) {
                    mma16816(acc[tm][tn], ah[tm], bh[tn]);
                    mma16816(acc[tm][tn], ah[tm], bl[tn]);
                    if (nProd == 3) mma16816(acc[tm][tn], al[tm], bh[tn]);
                }
        }
    }
    __syncthreads();

    #pragma unroll
    for (int tm = 0; tm < 2; tm++) {
        #pragma unroll
        for (int half = 0; half < 2; half++) {
            int m = m0 + wm * 32 + tm * 16 + (lane >> 2) + half * 8;
            #pragma unroll
            for (int tn = 0; tn < 8; tn++) {
                int n = n0 + wn * 64 + tn * 8 + (lane & 3) * 2;
                float v0 = alpha * acc[tm][tn][half * 2 + 0];
                float v1 = alpha * acc[tm][tn][half * 2 + 1];
                if (bias) { v0 += bias[n]; v1 += bias[n + 1]; }
                if (doRelu) { v0 = fmaxf(v0, 0.f); v1 = fmaxf(v1, 0.f); }
                long idx = (long)m * N + n;
                if (Cf) {
                    if (accFlag) { Cf[idx] += v0; Cf[idx + 1] += v1; }
                    else { Cf[idx] = v0; Cf[idx + 1] = v1; }
                } else {
                    __nv_bfloat16 h0 = __float2bfloat16(v0);
                    __nv_bfloat16 h1 = __float2bfloat16(v1);
                    __nv_bfloat162 hp; hp.x = h0; hp.y = h1;
                    *reinterpret_cast<__nv_bfloat162*>(&Chi[idx]) = hp;
                    __nv_bfloat162 lp;
                    lp.x = __float2bfloat16(v0 - __bfloat162float(h0));
                    lp.y = __float2bfloat16(v1 - __bfloat162float(h1));
                    *reinterpret_cast<__nv_bfloat162*>(&Clo[idx]) = lp;
                }
            }
        }
    }

    // fused per-CTA row-max / sum-exp partials (LSE)
    if (pmax) {
        float* sm8 = (float*)smem;                    // [128][8]
        float* rowred = (float*)(smem + 128 * 8 * 4); // [128]
        int slot = wn * 4 + (lane & 3);
        __syncthreads();
        #pragma unroll
        for (int tm = 0; tm < 2; tm++)
            #pragma unroll
            for (int half = 0; half < 2; half++) {
                int rl = wm * 32 + tm * 16 + (lane >> 2) + half * 8;
                float lm = -1e30f;
                #pragma unroll
                for (int tn = 0; tn < 8; tn++)
                    #pragma unroll
                    for (int e = 0; e < 2; e++)
                        lm = fmaxf(lm, alpha * acc[tm][tn][half * 2 + e]);
                sm8[rl * 8 + slot] = lm;
            }
        __syncthreads();
        if (tid < 128) {
            float mR = -1e30f;
            #pragma unroll
            for (int i = 0; i < 8; i++) mR = fmaxf(mR, sm8[tid * 8 + i]);
            rowred[tid] = mR;
        }
        __syncthreads();
        #pragma unroll
        for (int tm = 0; tm < 2; tm++)
            #pragma unroll
            for (int half = 0; half < 2; half++) {
                int rl = wm * 32 + tm * 16 + (lane >> 2) + half * 8;
                float rm = rowred[rl];
                float ls = 0.f;
                #pragma unroll
                for (int tn = 0; tn < 8; tn++)
                    #pragma unroll
                    for (int e = 0; e < 2; e++)
                        ls += expf(alpha * acc[tm][tn][half * 2 + e] - rm);
                sm8[rl * 8 + slot] = ls;
            }
        __syncthreads();
        if (tid < 128) {
            float sR = 0.f;
            #pragma unroll
            for (int i = 0; i < 8; i++) sR += sm8[tid * 8 + i];
            long r = m0 + tid;
            pmax[r * nxb + blockIdx.x] = rowred[tid];
            psum[r * nxb + blockIdx.x] = sR;
        }
    }
}

// ---------------- SIMT 64x64 tile core (small fp32 GEMMs) ------------------
__device__ __forceinline__ void gemm64_acc(
    const float* __restrict__ A, const float* __restrict__ Bm, bool transB,
    int N, int Kd, int m0, int n0, int rollL, int rollOff,
    float As[32][64], float Bs[32][64], float acc[4][4])
{
    int tid = threadIdx.x;
    int tx = tid & 15, ty = tid >> 4;
    int arow = tid >> 2, ak0 = (tid & 3) * 8;
    int gm = m0 + arow;
    if (rollL) {
        int g = gm / rollL, l = gm - g * rollL;
        l += rollOff; if (l >= rollL) l -= rollL;
        gm = g * rollL + l;
    }
    const float* Aptr = A + (long)gm * Kd + ak0;
    for (int k0 = 0; k0 < Kd; k0 += 32) {
        #pragma unroll
        for (int i = 0; i < 8; i += 4) {
            float4 v = *(const float4*)(Aptr + k0 + i);
            As[ak0+i+0][arow] = v.x; As[ak0+i+1][arow] = v.y;
            As[ak0+i+2][arow] = v.z; As[ak0+i+3][arow] = v.w;
        }
        if (transB) {
            int br = tid >> 2, bk0 = (tid & 3) * 8;
            const float* Bp = Bm + (long)(n0 + br) * Kd + k0 + bk0;
            #pragma unroll
            for (int i = 0; i < 8; i += 4) {
                float4 v = *(const float4*)(Bp + i);
                Bs[bk0+i+0][br] = v.x; Bs[bk0+i+1][br] = v.y;
                Bs[bk0+i+2][br] = v.z; Bs[bk0+i+3][br] = v.w;
            }
        } else {
            int bk = tid >> 3, bn0 = (tid & 7) * 8;
            const float* Bp = Bm + (long)(k0 + bk) * N + n0 + bn0;
            #pragma unroll
            for (int i = 0; i < 8; i += 4)
                *(float4*)&Bs[bk][bn0 + i] = *(const float4*)(Bp + i);
        }
        __syncthreads();
        #pragma unroll
        for (int k = 0; k < 32; k++) {
            float a[4], b[4];
            *(float4*)a = *(const float4*)&As[k][ty * 4];
            *(float4*)b = *(const float4*)&Bs[k][tx * 4];
            #pragma unroll
            for (int i = 0; i < 4; i++)
                #pragma unroll
                for (int j = 0; j < 4; j++)
                    acc[i][j] += a[i] * b[j];
        }
        __syncthreads();
    }
}

// pair_k: z=0: tmp1 = relu(roll(xsa,+1) @ wt); z=1: tmp2 = relu(roll(xsa,-1) @ wtc^T)
__global__ __launch_bounds__(256) void pair_k(
    const float* __restrict__ xsa, const float* __restrict__ wt,
    const float* __restrict__ wtc, float* __restrict__ tmp1, float* __restrict__ tmp2)
{
    __shared__ float As[32][64];
    __shared__ float Bs[32][64];
    int m0 = blockIdx.y * 64, n0 = blockIdx.x * 64;
    float acc[4][4] = {};
    float* C;
    if (blockIdx.z == 0) {
        gemm64_acc(xsa, wt, false, EE, EE, m0, n0, LL, LL - 1, As, Bs, acc);
        C = tmp1;
    } else {
        gemm64_acc(xsa, wtc, true, EE, EE, m0, n0, LL, 1, As, Bs, acc);
        C = tmp2;
    }
    int tid = threadIdx.x, tx = tid & 15, ty = tid >> 4;
    #pragma unroll
    for (int i = 0; i < 4; i++) {
        int m = m0 + ty * 4 + i;
        #pragma unroll
        for (int j = 0; j < 4; j++) {
            int n = n0 + tx * 4 + j;
            C[(long)m * EE + n] = fmaxf(acc[i][j], 0.f);
        }
    }
}

// sum3_k: xsad = tmp1 @ wtc + tmp2 @ wt^T + z @ wu^T + bt
__global__ __launch_bounds__(256) void sum3_k(
    const float* __restrict__ tmp1, const float* __restrict__ tmp2,
    const float* __restrict__ z, const float* __restrict__ wt,
    const float* __restrict__ wtc, const float* __restrict__ wu,
    const float* __restrict__ bt, float* __restrict__ xsad)
{
    __shared__ float As[32][64];
    __shared__ float Bs[32][64];
    int m0 = blockIdx.y * 64, n0 = blockIdx.x * 64;
    float acc[4][4] = {};
    gemm64_acc(tmp1, wtc, false, EE, EE, m0, n0, 0, 0, As, Bs, acc);
    gemm64_acc(tmp2, wt,  true,  EE, EE, m0, n0, 0, 0, As, Bs, acc);
    gemm64_acc(z,    wu,  true,  EE, EE, m0, n0, 0, 0, As, Bs, acc);
    int tid = threadIdx.x, tx = tid & 15, ty = tid >> 4;
    #pragma unroll
    for (int i = 0; i < 4; i++) {
        int m = m0 + ty * 4 + i;
        #pragma unroll
        for (int j = 0; j < 4; j++) {
            int n = n0 + tx * 4 + j;
            xsad[(long)m * EE + n] = acc[i][j] + bt[n];
        }
    }
}

// ---------------- split / transpose-split ----------------------------------
__global__ void split_k(const float* __restrict__ s, __nv_bfloat16* __restrict__ h,
                        __nv_bfloat16* __restrict__ l, long n)
{
    long i = blockIdx.x * 256L + threadIdx.x;
    if (i < n) {
        float v = s[i];
        __nv_bfloat16 a = __float2bfloat16(v);
        h[i] = a;
        l[i] = __float2bfloat16(v - __bfloat162float(a));
    }
}
__global__ void tsplit_k(const float* __restrict__ s, __nv_bfloat16* __restrict__ h,
                         __nv_bfloat16* __restrict__ l, int R, int C, long sS, long sD)
{
    __shared__ float t[32][33];
    int b = blockIdx.z;
    s += (long)b * sS; h += (long)b * sD; l += (long)b * sD;
    int r0 = blockIdx.y * 32, c0 = blockIdx.x * 32;
    int x = threadIdx.x, y = threadIdx.y;
    #pragma unroll
    for (int i = 0; i < 32; i += 8) t[y + i][x] = s[(long)(r0 + y + i) * C + c0 + x];
    __syncthreads();
    #pragma unroll
    for (int i = 0; i < 32; i += 8) {
        float v = t[x][y + i];
        __nv_bfloat16 a = __float2bfloat16(v);
        long idx = (long)(c0 + y + i) * R + r0 + x;
        h[idx] = a;
        l[idx] = __float2bfloat16(v - __bfloat162float(a));
    }
}

// ---------------- elementwise / reduction kernels --------------------------
__device__ __forceinline__ float blkSum256(float v) {
    __shared__ float sh[8];
    int lane = threadIdx.x & 31, w = threadIdx.x >> 5;
    #pragma unroll
    for (int o = 16; o; o >>= 1) v += __shfl_xor_sync(0xffffffffu, v, o);
    __syncthreads();
    if (lane == 0) sh[w] = v;
    __syncthreads();
    float r = sh[0];
    #pragma unroll
    for (int i = 1; i < 8; i++) r += sh[i];
    return r;
}
__device__ __forceinline__ float blkMax256(float v) {
    __shared__ float sh[8];
    int lane = threadIdx.x & 31, w = threadIdx.x >> 5;
    #pragma unroll
    for (int o = 16; o; o >>= 1) v = fmaxf(v, __shfl_xor_sync(0xffffffffu, v, o));
    __syncthreads();
    if (lane == 0) sh[w] = v;
    __syncthreads();
    float r = sh[0];
    #pragma unroll
    for (int i = 1; i < 8; i++) r = fmaxf(r, sh[i]);
    return r;
}
__device__ __forceinline__ void emit_planes(__nv_bfloat16* h, __nv_bfloat16* l,
                                            long idx, float v) {
    __nv_bfloat16 a = __float2bfloat16(v);
    h[idx] = a;
    l[idx] = __float2bfloat16(v - __bfloat162float(a));
}

__global__ void embed_norm_k(const int* __restrict__ masked, const float* __restrict__ embed,
                             float* __restrict__ z, float* __restrict__ xsa,
                             __nv_bfloat16* __restrict__ xh, __nv_bfloat16* __restrict__ xl)
{
    long row = blockIdx.x; int t = threadIdx.x;
    float v = embed[(long)masked[row] * EE + t];
    float mean = blkSum256(v) * (1.f / EE);
    float d = v - mean;
    float var = fmaxf(blkSum256(d * d) * (1.f / (EE - 1)), 0.f);
    float o = v / (1.f + sqrtf(var));
    long i = row * EE + t;
    z[i] = o;
    xsa[i] = o;
    emit_planes(xh, xl, i, o);
}

__global__ void softmax512_k(const float* __restrict__ h,
                             __nv_bfloat16* __restrict__ ph)
{
    long row = blockIdx.x;
    const float* p = h + row * 512;
    int t = threadIdx.x;
    float a = p[t], b = p[t + 256];
    float m = blkMax256(fmaxf(a, b));
    float ea = __expf(a - m), eb = __expf(b - m);
    float s = blkSum256(ea + eb);
    float inv = 1.f / s;
    ph[row * 512 + t] = __float2bfloat16(ea * inv);
    ph[row * 512 + t + 256] = __float2bfloat16(eb * inv);
}

__global__ void update_k(const float* __restrict__ xsad, const float* __restrict__ xid,
                         float* __restrict__ xsa,
                         __nv_bfloat16* __restrict__ xh, __nv_bfloat16* __restrict__ xl)
{
    long row = blockIdx.x; int t = threadIdx.x;
    long i = row * EE + t;
    const long S = (long)BL * EE;
    float s = xsad[i] + ((xid[i] + xid[i + S]) + (xid[i + 2 * S] + xid[i + 3 * S]));
    float mean = blkSum256(s) * (1.f / EE);
    float d = s - mean;
    float var = fmaxf(blkSum256(d * d) * (1.f / (EE - 1)), 0.f);
    float a = s / (1.f + sqrtf(var));
    float x = xsa[i] + 0.05f * a;
    float mean2 = blkSum256(x) * (1.f / EE);
    float d2 = x - mean2;
    float var2 = fmaxf(blkSum256(d2 * d2) * (1.f / (EE - 1)), 0.f);
    float o = x / (1.f + sqrtf(var2));
    xsa[i] = o;
    emit_planes(xh, xl, i, o);
}

__global__ void gather_lptok_k(const float* __restrict__ xsa, const int* __restrict__ mask,
                               __nv_bfloat16* __restrict__ h, __nv_bfloat16* __restrict__ l)
{
    int r = blockIdx.x;
    int b = r / LMM, lm = r % LMM;
    int pos = mask[b * LMM + lm];
    int t = threadIdx.x;
    float v = xsa[((long)b * LL + pos) * EE + t];
    emit_planes(h, l, (long)r * EE + t, v);
}

__global__ void lse_reduce_k(const float* __restrict__ pmax, const float* __restrict__ psum,
                             float* __restrict__ lse)
{
    long row = blockIdx.x;
    int t = threadIdx.x;
    const float* pm = pmax + row * NXB;
    const float* ps = psum + row * NXB;
    float m = -1e30f;
    for (int i = t; i < NXB; i += 256) m = fmaxf(m, pm[i]);
    m = blkMax256(m);
    float s = 0.f;
    for (int i = t; i < NXB; i += 256) s += ps[i] * expf(pm[i] - m);
    s = blkSum256(s);
    if (!t) lse[row] = m + logf(s);
}

__global__ void final_k(const float* __restrict__ logits, const float* __restrict__ lse,
                        const int* __restrict__ unmasked, const int* __restrict__ mask,
                        float* __restrict__ out)
{
    int b = blockIdx.x, lm = threadIdx.x;
    int pos = mask[b * LMM + lm];
    int tgt = unmasked[b * LL + pos];
    float v[KNN]; float m = -1e30f;
    #pragma unroll
    for (int kn = 0; kn < KNN; kn++) {
        int n = b * (LMM * KNN) + lm * KNN + kn;
        v[kn] = logits[(long)n * GG + tgt] - lse[n];
        m = fmaxf(m, v[kn]);
    }
    float s = 0.f;
    #pragma unroll
    for (int kn = 0; kn < KNN; kn++) s += expf(v[kn] - m);
    float cent = m + logf(s) - logf((float)KNN);
    __shared__ float sh[LMM];
    sh[lm] = cent; __syncthreads();
    for (int o = 32; o; o >>= 1) { if (lm < o) sh[lm] += sh[lm + o]; __syncthreads(); }
    if (!lm) out[b] = -sh[0] / (float)LMM;
}

// ---------------- host orchestration ---------------------------------------
typedef __nv_bfloat16 bf;
template <typename T> static inline T* sym(const void* s) {
    void* p = nullptr; cudaGetSymbolAddress(&p, s); return (T*)p;
}
static inline void tc(cudaStream_t st, const bf* Ah, const bf* Al, const bf* Bh, const bf* Bl,
                      const float* bias, float* Cf, bf* Ch, bf* Cl,
                      int M, int N, int K, long sA, long sB, long sC, int batch,
                      float alpha, int relu, int accF = 0, int splitK = 1,
                      float* pmax = nullptr, float* psum = nullptr, int nProd = 3)
{
    int kcT = 1;
    int zdim = batch;
    if (splitK > 1) {
        int nbAll = K >> 6;
        kcT = (nbAll + splitK - 1) / splitK;
        zdim = splitK;
    }
    dim3 g(N / 128, M / 128, zdim);
    tc_gemm<<<g, 256, TCSM, st>>>(Ah, Al, Bh, Bl, bias, Cf, Ch, Cl, pmax, psum, N / 128,
                                  M, N, K, sA, sB, sC, alpha, relu, accF, splitK, kcT, nProd);
}

extern "C" void kernel_launch(void* const* d_in, const int* in_sizes, int n_in,
                              void* d_out, int out_size)
{
    const int*   masked   = (const int*)  d_in[0];
    const int*   unmasked = (const int*)  d_in[1];
    const int*   mask     = (const int*)  d_in[2];
    const float* embed    = (const float*)d_in[3];
    const float* Wt       = (const float*)d_in[4];
    const float* bt       = (const float*)d_in[5];
    const float* Wtc      = (const float*)d_in[6];
    const float* Wq       = (const float*)d_in[7];
    const float* Wd       = (const float*)d_in[8];
    const float* Wo       = (const float*)d_in[9];
    const float* Wu       = (const float*)d_in[10];
    const float* Wem      = (const float*)d_in[11];
    const float* Wkc      = (const float*)d_in[12];
    const float* bkc      = (const float*)d_in[13];
    float* out = (float*)d_out;

    static bool inited = false;
    static cudaStream_t s2 = nullptr;
    static cudaEvent_t evFork = nullptr, evS = nullptr;
    if (!inited) {
        cudaFuncSetAttribute(tc_gemm, cudaFuncAttributeMaxDynamicSharedMemorySize, TCSM);
        cudaStreamCreateWithFlags(&s2, cudaStreamNonBlocking);
        cudaEventCreateWithFlags(&evFork, cudaEventDisableTiming);
        cudaEventCreateWithFlags(&evS, cudaEventDisableTiming);
        inited = true;
    }
    cudaStream_t s0 = 0;

    float *z = sym<float>(g_z), *xsa = sym<float>(g_xsa), *xsad = sym<float>(g_xsad);
    float *tmp1 = sym<float>(g_tmp1), *tmp2 = sym<float>(g_tmp2), *xid = sym<float>(g_xid);
    float *h = sym<float>(g_h), *logits = sym<float>(g_logits), *lse = sym<float>(g_lse);
    float *pmax = sym<float>(g_pmax), *psum = sym<float>(g_psum);
    bf *xsaP = sym<bf>(g_xsaP), *xsaTP = sym<bf>(g_xsaTP);
    bf *qP = sym<bf>(g_qP), *pP = sym<bf>(g_pP), *yP = sym<bf>(g_yP), *ydP = sym<bf>(g_ydP);
    bf *wqP = sym<bf>(g_wqP), *wdP = sym<bf>(g_wdP), *woTP = sym<bf>(g_woTP);
    bf *embP = sym<bf>(g_embP), *kcP = sym<bf>(g_kcP), *wemTP = sym<bf>(g_wemTP);
    bf *lptP = sym<bf>(g_lptP), *xx1P = sym<bf>(g_xx1P), *tbP = sym<bf>(g_tbP);
    bf *xx2P = sym<bf>(g_xx2P), *vP = sym<bf>(g_vP);

    embed_norm_k<<<BL, 256, 0, s0>>>(masked, embed, z, xsa, xsaP, xsaP + PXSA);
    split_k<<<(PWQA + 255) / 256, 256, 0, s0>>>(Wq, wqP, wqP + PWQA, PWQA);

    for (int d = 0; d < DL; d++) {
        const float* wt  = Wt  + (long)d * EE * EE;
        const float* btd = bt  + (long)d * EE;
        const float* wtc = Wtc + (long)d * EE * EE;
        const float* wu  = Wu  + (long)d * EE * EE;
        const bf* wqh = wqP + (long)d * KE * EE;  const bf* wql = wqh + PWQA;
        const bf* wdh = wdP + (long)d * KE * KE;  const bf* wdl = wdh + PWDA;
        const bf* woh = woTP + (long)d * EE * KE; const bf* wol = woh + PWOA;

        cudaEventRecord(evFork, s0);
        cudaStreamWaitEvent(s2, evFork, 0);
        if (d == 0) {
            split_k<<<(PWDA + 255) / 256, 256, 0, s2>>>(Wd, wdP, wdP + PWDA, PWDA);
            split_k<<<(PEMB + 255) / 256, 256, 0, s2>>>(embed, embP, embP + PEMB, PEMB);
            split_k<<<(PKC + 255) / 256, 256, 0, s2>>>(Wkc, kcP, kcP + PKC, PKC);
            { dim3 b(32, 8), g(EE / 32, KE / 32, DL);
              tsplit_k<<<g, b, 0, s2>>>(Wo, woTP, woTP + PWOA, KE, EE, (long)KE * EE, (long)EE * KE); }
            { dim3 b(32, 8), g(EE / 32, EE / 32, 1);
              tsplit_k<<<g, b, 0, s2>>>(Wem, wemTP, wemTP + PWEM, EE, EE, 0, 0); }
        }
        { dim3 b(32, 8), g(EE / 32, LL / 32, BB);
          tsplit_k<<<g, b, 0, s2>>>(xsa, xsaTP, xsaTP + PXSAT, LL, EE, (long)LL * EE, (long)EE * LL); }
        { dim3 g(EE / 64, BL / 64, 2);
          pair_k<<<g, 256, 0, s2>>>(xsa, wt, wtc, tmp1, tmp2); }
        { dim3 g(EE / 64, BL / 64, 1);
          sum3_k<<<g, 256, 0, s2>>>(tmp1, tmp2, z, wt, wtc, wu, btd, xsad); }
        cudaEventRecord(evS, s2);

        tc(s0, xsaP, xsaP + PXSA, wqh, wql, nullptr, nullptr, qP, qP + PQ,
           BL, KE, EE, 0, 0, 0, 1, 1.f, 0);
        // h = (1/16) q @ xsa^T — 2-product mode (q hi plane only)
        tc(s0, qP, qP + PQ, xsaP, xsaP + PXSA, nullptr, h, nullptr, nullptr,
           LK, LL, EE, (long)LK * EE, (long)LL * EE, (long)LK * LL, BB, 1.f / 16.f, 0,
           0, 1, nullptr, nullptr, /*nProd=*/2);
        softmax512_k<<<BB * LK, 256, 0, s0>>>(h, pP);

        cudaStreamWaitEvent(s0, evS, 0);

        // y = P @ xsa — 2-product mode (P hi plane only)
        tc(s0, pP, pP, xsaTP, xsaTP + PXSAT, nullptr, nullptr, yP, yP + PY,
           LK, EE, LL, (long)LK * LL, (long)EE * LL, (long)LK * EE, BB, 1.f, 0,
           0, 1, nullptr, nullptr, /*nProd=*/2);
        // yd = relu(y @ wd.T) — 2-product mode (y hi plane only)
        tc(s0, yP, yP + PY, wdh, wdl, nullptr, nullptr, ydP, ydP + PYD,
           BL, KE, KE, 0, 0, 0, 1, 1.f, 1,
           0, 1, nullptr, nullptr, /*nProd=*/2);
        // xid = yd @ wo — deterministic split-K=4 into 4 slabs (stride BL*EE)
        tc(s0, ydP, ydP + PYD, woh, wol, nullptr, xid, nullptr, nullptr,
           BL, EE, KE, 0, 0, (long)BL * EE, 1, 1.f, 0, 0, /*splitK=*/4);
        update_k<<<BL, 256, 0, s0>>>(xsad, xid, xsa, xsaP, xsaP + PXSA);
    }

    // ---- head ----
    cudaEventRecord(evFork, s0);
    cudaStreamWaitEvent(s2, evFork, 0);
    { dim3 b(32, 8), g(EE / 32, LL / 32, BB);
      tsplit_k<<<g, b, 0, s2>>>(xsa, xsaTP, xsaTP + PXSAT, LL, EE, (long)LL * EE, (long)EE * LL); }
    cudaEventRecord(evS, s2);

    gather_lptok_k<<<BB * LMM, 256, 0, s0>>>(xsa, mask, lptP, lptP + PLPT);
    tc(s0, lptP, lptP + PLPT, kcP, kcP + PKC, bkc, nullptr, xx1P, xx1P + PXX1,
       BB * LMM, KNN * EE, EE, 0, 0, 0, 1, 1.f, 0);
    tc(s0, xx1P, xx1P + PXX1, xsaP, xsaP + PXSA, nullptr, nullptr, tbP, tbP + PTB,
       LMM * KNN, LL, EE, (long)LMM * KNN * EE, (long)LL * EE, (long)LMM * KNN * LL, BB, 1.f, 0);
    cudaStreamWaitEvent(s0, evS, 0);
    tc(s0, tbP, tbP + PTB, xsaTP, xsaTP + PXSAT, nullptr, nullptr, xx2P, xx2P + PXX2,
       LMM * KNN, EE, LL, (long)LMM * KNN * LL, (long)EE * LL, (long)LMM * KNN * EE, BB, 1.f, 0);
    tc(s0, xx2P, xx2P + PXX2, wemTP, wemTP + PWEM, nullptr, nullptr, vP, vP + PV,
       BB * LMM * KNN, EE, EE, 0, 0, 0, 1, 1.f, 0);
    tc(s0, vP, vP + PV, embP, embP + PEMB, nullptr, logits, nullptr, nullptr,
       NR, GG, EE, 0, 0, 0, 1, 1.f, 0, 0, 1, pmax, psum);
    lse_reduce_k<<<NR, 256, 0, s0>>>(pmax, psum, lse);
    final_k<<<BB, LMM, 0, s0>>>(logits, lse, unmasked, mask, out);
}